// round 1
// baseline (speedup 1.0000x reference)
#include <cuda_runtime.h>
#include <math.h>

// ---------------- problem constants ----------------
#define NHH   4
#define DD    256
#define NN    8192
#define TT    2048
#define VOC   256
#define SPLITK 8
#define KSPL  (NHH * NN / SPLITK)   // 4096
#define LNEPS 1e-5f
#define TWO_PI_F 6.28318530717958647692f

// ---------------- scratch (static device globals; no cudaMalloc allowed) ----
__device__ float g_x[TT * DD];                          // current residual x  (2 MB)
__device__ float g_xs[(size_t)NHH * TT * NN];           // x_sparse            (256 MB)
__device__ float g_qr[(size_t)NHH * TT * NN];           // QR, later reused as xy (256 MB)
__device__ float g_scores[(size_t)NHH * TT * TT];       // attention scores    (64 MB)
__device__ float g_ykv[(size_t)NHH * TT * DD];          // yKV (LN in place)   (8 MB)
__device__ float g_part[(size_t)SPLITK * TT * DD];      // decoder split-K partials (16 MB)

enum { EM_NONE = 0, EM_MASK, EM_YKV, EM_RELU_ROPE, EM_RELU_MULXY };

// ---------------- block reduction over 256 threads ----------------
__device__ __forceinline__ float blk_sum(float v, float* sb) {
    int tid = threadIdx.x;
#pragma unroll
    for (int o = 16; o > 0; o >>= 1) v += __shfl_down_sync(0xffffffffu, v, o);
    if ((tid & 31) == 0) sb[tid >> 5] = v;
    __syncthreads();
    if (tid < 32) {
        float w = (tid < 8) ? sb[tid] : 0.f;
#pragma unroll
        for (int o = 4; o > 0; o >>= 1) w += __shfl_down_sync(0xffffffffu, w, o);
        if (tid == 0) sb[0] = w;
    }
    __syncthreads();
    float r = sb[0];
    __syncthreads();
    return r;
}

// ---------------- generic 128x128x8 fp32 SGEMM with fused epilogues --------
// C[M,Nc] = A[M,K] * B  (TRANSB==0: B is [K,Nc] row-major; TRANSB==1: B is [Nc,K])
// grid = (Nc/128, M/128, Z); per-z pointer offsets offAz/offBz/offCz (elements).
template <int TRANSB, int MODE>
__global__ void __launch_bounds__(256)
sgemm_kernel(const float* __restrict__ A, const float* __restrict__ B,
             float* __restrict__ C, int K,
             int lda, int ldb, int ldc,
             long offAz, long offBz, long offCz)
{
    const int z = blockIdx.z;
    A += (long)z * offAz;
    B += (long)z * offBz;
    C += (long)z * offCz;

    const int br = blockIdx.y, bc = blockIdx.x;
    const int row0 = br * 128, col0 = bc * 128;
    const int tid = threadIdx.x;
    const int tx = tid & 15, ty = tid >> 4;

    if (MODE == EM_MASK) {
        if (bc > br) {  // tile entirely above the strict-lower mask: write zeros
            float4 z4 = make_float4(0.f, 0.f, 0.f, 0.f);
#pragma unroll
            for (int i = 0; i < 8; i++) {
                long base = (long)(row0 + ty * 8 + i) * ldc + col0 + tx * 8;
                *(float4*)(C + base)     = z4;
                *(float4*)(C + base + 4) = z4;
            }
            return;
        }
    }

    int Keff = K;
    if (MODE == EM_YKV) Keff = row0 + 128;  // scores[t,s]==0 for s>=t

    __shared__ __align__(16) float As[8][132];
    __shared__ __align__(16) float Bs[8][132];

    float acc[8][8] = {};

    const int ar = tid >> 1;           // 0..127
    const int ak = (tid & 1) * 4;      // 0 or 4
    const int bkr = tid >> 5;          // 0..7
    const int bcc = (tid & 31) * 4;    // 0..124

    const float* Ap = A + (long)(row0 + ar) * lda + ak;
    const float* Bp;
    if (TRANSB) Bp = B + (long)(col0 + ar) * ldb + ak;
    else        Bp = B + (long)bkr * ldb + col0 + bcc;

    for (int k0 = 0; k0 < Keff; k0 += 8) {
        float4 a4 = *(const float4*)Ap;  Ap += 8;
        float4 b4;
        if (TRANSB) { b4 = *(const float4*)Bp; Bp += 8; }
        else        { b4 = *(const float4*)Bp; Bp += (long)8 * ldb; }

        As[ak + 0][ar] = a4.x; As[ak + 1][ar] = a4.y;
        As[ak + 2][ar] = a4.z; As[ak + 3][ar] = a4.w;
        if (TRANSB) {
            Bs[ak + 0][ar] = b4.x; Bs[ak + 1][ar] = b4.y;
            Bs[ak + 2][ar] = b4.z; Bs[ak + 3][ar] = b4.w;
        } else {
            Bs[bkr][bcc + 0] = b4.x; Bs[bkr][bcc + 1] = b4.y;
            Bs[bkr][bcc + 2] = b4.z; Bs[bkr][bcc + 3] = b4.w;
        }
        __syncthreads();

#pragma unroll
        for (int k = 0; k < 8; k++) {
            float a[8], b[8];
            *(float4*)&a[0] = *(const float4*)&As[k][ty * 8];
            *(float4*)&a[4] = *(const float4*)&As[k][ty * 8 + 4];
            *(float4*)&b[0] = *(const float4*)&Bs[k][tx * 8];
            *(float4*)&b[4] = *(const float4*)&Bs[k][tx * 8 + 4];
#pragma unroll
            for (int i = 0; i < 8; i++)
#pragma unroll
                for (int j = 0; j < 8; j++)
                    acc[i][j] = fmaf(a[i], b[j], acc[i][j]);
        }
        __syncthreads();
    }

    // ---------------- epilogues ----------------
    if (MODE == EM_NONE || MODE == EM_YKV) {
#pragma unroll
        for (int i = 0; i < 8; i++) {
            long base = (long)(row0 + ty * 8 + i) * ldc + col0 + tx * 8;
            *(float4*)(C + base)     = make_float4(acc[i][0], acc[i][1], acc[i][2], acc[i][3]);
            *(float4*)(C + base + 4) = make_float4(acc[i][4], acc[i][5], acc[i][6], acc[i][7]);
        }
    } else if (MODE == EM_MASK) {
#pragma unroll
        for (int i = 0; i < 8; i++) {
            int t = row0 + ty * 8 + i;
            float v[8];
#pragma unroll
            for (int j = 0; j < 8; j++) {
                int s = col0 + tx * 8 + j;
                v[j] = (t > s) ? acc[i][j] : 0.f;
            }
            long base = (long)t * ldc + col0 + tx * 8;
            *(float4*)(C + base)     = make_float4(v[0], v[1], v[2], v[3]);
            *(float4*)(C + base + 4) = make_float4(v[4], v[5], v[6], v[7]);
        }
    } else if (MODE == EM_RELU_ROPE) {
        // C = x_sparse (relu), also write QR = rope(x_sparse) to g_qr (+ z stride)
        float* Q = g_qr + (long)z * ((long)TT * NN);
        float fr[4];
#pragma unroll
        for (int p = 0; p < 4; p++) {
            int n0 = col0 + tx * 8 + p * 2;  // even; q = (n//2)*2 == n0 for the pair
            float a = (float)exp2(-(double)n0 / 512.0);  // THETA^{-q/N}, THETA=2^16
            fr[p] = a / TWO_PI_F;
        }
#pragma unroll
        for (int i = 0; i < 8; i++) {
            int t = row0 + ty * 8 + i;
            float v[8];
#pragma unroll
            for (int j = 0; j < 8; j++) v[j] = fmaxf(acc[i][j], 0.f);
            long base = (long)t * ldc + col0 + tx * 8;
            *(float4*)(C + base)     = make_float4(v[0], v[1], v[2], v[3]);
            *(float4*)(C + base + 4) = make_float4(v[4], v[5], v[6], v[7]);
            float q[8];
#pragma unroll
            for (int p = 0; p < 4; p++) {
                float ph   = (float)t * fr[p];
                float frac = ph - floorf(ph);
                float ang  = frac * TWO_PI_F;
                float si, co;
                sincosf(ang, &si, &co);
                q[2 * p]     = v[2 * p] * co - v[2 * p + 1] * si;
                q[2 * p + 1] = v[2 * p + 1] * co + v[2 * p] * si;
            }
            *(float4*)(Q + base)     = make_float4(q[0], q[1], q[2], q[3]);
            *(float4*)(Q + base + 4) = make_float4(q[4], q[5], q[6], q[7]);
        }
    } else if (MODE == EM_RELU_MULXY) {
        // C = xy laid out [t, h*N+n]; acc = yKV@encoder_v pre-relu; multiply by x_sparse
        const float* xsrc = g_xs + (long)z * ((long)TT * NN);
#pragma unroll
        for (int i = 0; i < 8; i++) {
            int t = row0 + ty * 8 + i;
            long sbase = (long)t * NN + col0 + tx * 8;
            float4 x0 = *(const float4*)(xsrc + sbase);
            float4 x1 = *(const float4*)(xsrc + sbase + 4);
            float4 o0, o1;
            o0.x = fmaxf(acc[i][0], 0.f) * x0.x;
            o0.y = fmaxf(acc[i][1], 0.f) * x0.y;
            o0.z = fmaxf(acc[i][2], 0.f) * x0.z;
            o0.w = fmaxf(acc[i][3], 0.f) * x0.w;
            o1.x = fmaxf(acc[i][4], 0.f) * x1.x;
            o1.y = fmaxf(acc[i][5], 0.f) * x1.y;
            o1.z = fmaxf(acc[i][6], 0.f) * x1.z;
            o1.w = fmaxf(acc[i][7], 0.f) * x1.w;
            long obase = (long)t * ldc + col0 + tx * 8;  // C already offset by z*NN
            *(float4*)(C + obase)     = o0;
            *(float4*)(C + obase + 4) = o1;
        }
    }
}

// ---------------- embedding gather + LayerNorm ----------------
__global__ void embed_ln_kernel(const int* __restrict__ idx,
                                const float* __restrict__ embed)
{
    __shared__ float sb[8];
    int t = blockIdx.x, d = threadIdx.x;
    float v   = embed[idx[t] * DD + d];
    float mu  = blk_sum(v, sb) * (1.f / DD);
    float dv  = v - mu;
    float var = blk_sum(dv * dv, sb) * (1.f / DD);
    g_x[t * DD + d] = dv / sqrtf(var + LNEPS);
}

// ---------------- in-place row LayerNorm (D=256) ----------------
__global__ void ln_rows_kernel(float* __restrict__ buf)
{
    __shared__ float sb[8];
    long r = blockIdx.x;
    int  d = threadIdx.x;
    float v   = buf[r * DD + d];
    float mu  = blk_sum(v, sb) * (1.f / DD);
    float dv  = v - mu;
    float var = blk_sum(dv * dv, sb) * (1.f / DD);
    buf[r * DD + d] = dv / sqrtf(var + LNEPS);
}

// ---------------- split-K reduce + ln(yMLP), x = ln(x + ln(yMLP)) ----------
__global__ void mlp_finish_kernel()
{
    __shared__ float sb[8];
    int t = blockIdx.x, d = threadIdx.x;
    float s = 0.f;
#pragma unroll
    for (int kz = 0; kz < SPLITK; kz++)
        s += g_part[(size_t)kz * TT * DD + t * DD + d];

    float mu  = blk_sum(s, sb) * (1.f / DD);
    float dv  = s - mu;
    float var = blk_sum(dv * dv, sb) * (1.f / DD);
    float a   = dv / sqrtf(var + LNEPS);

    float b = g_x[t * DD + d] + a;
    mu  = blk_sum(b, sb) * (1.f / DD);
    dv  = b - mu;
    var = blk_sum(dv * dv, sb) * (1.f / DD);
    g_x[t * DD + d] = dv / sqrtf(var + LNEPS);
}

// ---------------- launch ----------------
extern "C" void kernel_launch(void* const* d_in, const int* in_sizes, int n_in,
                              void* d_out, int out_size)
{
    (void)in_sizes; (void)n_in; (void)out_size;
    const int*   idx       = (const int*)d_in[0];
    const float* embed     = (const float*)d_in[1];
    const float* encoder   = (const float*)d_in[2];
    const float* encoder_v = (const float*)d_in[3];
    const float* decoder   = (const float*)d_in[4];
    const float* lm_head   = (const float*)d_in[5];
    float*       out       = (float*)d_out;

    float *x, *xs, *qr, *scores, *ykv, *part;
    cudaGetSymbolAddress((void**)&x,      g_x);
    cudaGetSymbolAddress((void**)&xs,     g_xs);
    cudaGetSymbolAddress((void**)&qr,     g_qr);
    cudaGetSymbolAddress((void**)&scores, g_scores);
    cudaGetSymbolAddress((void**)&ykv,    g_ykv);
    cudaGetSymbolAddress((void**)&part,   g_part);

    embed_ln_kernel<<<TT, 256>>>(idx, embed);

    for (int l = 0; l < 2; l++) {
        // x_sparse[h] = relu(x @ encoder[h]); QR = rope(x_sparse)
        sgemm_kernel<0, EM_RELU_ROPE><<<dim3(NN / 128, TT / 128, NHH), 256>>>(
            x, encoder, xs, DD, DD, NN, NN,
            0L, (long)DD * NN, (long)TT * NN);

        // scores[h] = mask .* (QR @ QR^T)
        sgemm_kernel<1, EM_MASK><<<dim3(TT / 128, TT / 128, NHH), 256>>>(
            qr, qr, scores, NN, NN, NN, TT,
            (long)TT * NN, (long)TT * NN, (long)TT * TT);

        // yKV[h] = scores @ x   (K loop bounded by causal structure)
        sgemm_kernel<0, EM_YKV><<<dim3(DD / 128, TT / 128, NHH), 256>>>(
            scores, x, ykv, TT, TT, DD, DD,
            (long)TT * TT, 0L, (long)TT * DD);

        // LayerNorm yKV rows
        ln_rows_kernel<<<NHH * TT, 256>>>(ykv);

        // xy[t, h*N+n] = relu(yKV @ encoder_v[h]) * x_sparse   (into qr buffer)
        sgemm_kernel<0, EM_RELU_MULXY><<<dim3(NN / 128, TT / 128, NHH), 256>>>(
            ykv, encoder_v, qr, DD, DD, NN, NHH * NN,
            (long)TT * DD, (long)DD * NN, (long)NN);

        // yMLP partials = xy @ decoder  (split-K over 8 chunks of 4096)
        sgemm_kernel<0, EM_NONE><<<dim3(DD / 128, TT / 128, SPLITK), 256>>>(
            qr, decoder, part, KSPL, NHH * NN, DD, DD,
            (long)KSPL, (long)KSPL * DD, (long)TT * DD);

        // x = ln(x + ln(sum(partials)))
        mlp_finish_kernel<<<TT, 256>>>();
    }

    // logits = x @ lm_head
    sgemm_kernel<0, EM_NONE><<<dim3(VOC / 128, TT / 128, 1), 256>>>(
        x, lm_head, out, DD, DD, VOC, VOC, 0L, 0L, 0L);
}

// round 2
// speedup vs baseline: 1.0350x; 1.0350x over previous
#include <cuda_runtime.h>
#include <math.h>

// ---------------- problem constants ----------------
#define NHH   4
#define DD    256
#define NN    8192
#define TT    2048
#define VOC   256
#define SPLITK 8
#define KSPL  (NHH * NN / SPLITK)   // 4096
#define LNEPS 1e-5f
#define TWO_PI_F 6.28318530717958647692f

// ---------------- scratch (static device globals; no cudaMalloc allowed) ----
__device__ float g_x[TT * DD];                          // current residual x  (2 MB)
__device__ float g_xs[(size_t)NHH * TT * NN];           // x_sparse            (256 MB)
__device__ float g_qr[(size_t)NHH * TT * NN];           // QR, later reused as xy (256 MB)
__device__ float g_scores[(size_t)NHH * TT * TT];       // attention scores    (64 MB)
__device__ float g_ykv[(size_t)NHH * TT * DD];          // yKV (LN in place)   (8 MB)
__device__ float g_part[(size_t)SPLITK * TT * DD];      // decoder split-K partials (16 MB)

enum { EM_NONE = 0, EM_MASK, EM_YKV, EM_RELU_ROPE, EM_RELU_MULXY };

// ---------------- packed f32x2 helpers (SASS FFMA2 path) ----------------
typedef unsigned long long u64;

__device__ __forceinline__ void ffma2(u64& d, u64 a, u64 b) {
    asm("fma.rn.f32x2 %0, %1, %2, %0;" : "+l"(d) : "l"(a), "l"(b));
}
__device__ __forceinline__ u64 dup2(float x) {
    u64 r;
    asm("mov.b64 %0, {%1, %1};" : "=l"(r) : "r"(__float_as_uint(x)));
    return r;
}
__device__ __forceinline__ void unpack2(u64 v, float& lo, float& hi) {
    unsigned a, b;
    asm("mov.b64 {%0, %1}, %2;" : "=r"(a), "=r"(b) : "l"(v));
    lo = __uint_as_float(a);
    hi = __uint_as_float(b);
}

// ---------------- block reduction over 256 threads ----------------
__device__ __forceinline__ float blk_sum(float v, float* sb) {
    int tid = threadIdx.x;
#pragma unroll
    for (int o = 16; o > 0; o >>= 1) v += __shfl_down_sync(0xffffffffu, v, o);
    if ((tid & 31) == 0) sb[tid >> 5] = v;
    __syncthreads();
    if (tid < 32) {
        float w = (tid < 8) ? sb[tid] : 0.f;
#pragma unroll
        for (int o = 4; o > 0; o >>= 1) w += __shfl_down_sync(0xffffffffu, w, o);
        if (tid == 0) sb[0] = w;
    }
    __syncthreads();
    float r = sb[0];
    __syncthreads();
    return r;
}

// ---------------- generic 128x128x8 fp32 SGEMM with fused epilogues --------
// C[M,Nc] = A[M,K] * B  (TRANSB==0: B is [K,Nc] row-major; TRANSB==1: B is [Nc,K])
// grid = (Nc/128, M/128, Z); per-z pointer offsets offAz/offBz/offCz (elements).
// Inner product uses packed fma.rn.f32x2 (FFMA2) for 2x fp32 throughput.
template <int TRANSB, int MODE>
__global__ void __launch_bounds__(256)
sgemm_kernel(const float* __restrict__ A, const float* __restrict__ B,
             float* __restrict__ C, int K,
             int lda, int ldb, int ldc,
             long offAz, long offBz, long offCz)
{
    const int z = blockIdx.z;
    A += (long)z * offAz;
    B += (long)z * offBz;
    C += (long)z * offCz;

    const int br = blockIdx.y, bc = blockIdx.x;
    const int row0 = br * 128, col0 = bc * 128;
    const int tid = threadIdx.x;
    const int tx = tid & 15, ty = tid >> 4;

    if (MODE == EM_MASK) {
        if (bc > br) return;  // tile entirely above strict-lower mask; never read
    }

    int Keff = K;
    if (MODE == EM_YKV) Keff = row0 + 128;  // scores[t,s]==0 for s>=t

    __shared__ __align__(16) float As[8][132];
    __shared__ __align__(16) float Bs[8][132];

    u64 acc2[8][4];
#pragma unroll
    for (int i = 0; i < 8; i++)
#pragma unroll
        for (int j = 0; j < 4; j++) acc2[i][j] = 0ull;

    const int ar = tid >> 1;           // 0..127
    const int ak = (tid & 1) * 4;      // 0 or 4
    const int bkr = tid >> 5;          // 0..7
    const int bcc = (tid & 31) * 4;    // 0..124

    const float* Ap = A + (long)(row0 + ar) * lda + ak;
    const float* Bp;
    if (TRANSB) Bp = B + (long)(col0 + ar) * ldb + ak;
    else        Bp = B + (long)bkr * ldb + col0 + bcc;

    // prefetch chunk 0 into regs
    float4 a4 = *(const float4*)Ap;  Ap += 8;
    float4 b4;
    if (TRANSB) { b4 = *(const float4*)Bp; Bp += 8; }
    else        { b4 = *(const float4*)Bp; Bp += (long)8 * ldb; }

    for (int k0 = 0; k0 < Keff; k0 += 8) {
        // stage current chunk to smem
        As[ak + 0][ar] = a4.x; As[ak + 1][ar] = a4.y;
        As[ak + 2][ar] = a4.z; As[ak + 3][ar] = a4.w;
        if (TRANSB) {
            Bs[ak + 0][ar] = b4.x; Bs[ak + 1][ar] = b4.y;
            Bs[ak + 2][ar] = b4.z; Bs[ak + 3][ar] = b4.w;
        } else {
            Bs[bkr][bcc + 0] = b4.x; Bs[bkr][bcc + 1] = b4.y;
            Bs[bkr][bcc + 2] = b4.z; Bs[bkr][bcc + 3] = b4.w;
        }
        __syncthreads();

        // prefetch next chunk during compute (hides global-load latency)
        if (k0 + 8 < Keff) {
            a4 = *(const float4*)Ap;  Ap += 8;
            if (TRANSB) { b4 = *(const float4*)Bp; Bp += 8; }
            else        { b4 = *(const float4*)Bp; Bp += (long)8 * ldb; }
        }

#pragma unroll
        for (int k = 0; k < 8; k++) {
            float a[8];
            *(float4*)&a[0] = *(const float4*)&As[k][ty * 8];
            *(float4*)&a[4] = *(const float4*)&As[k][ty * 8 + 4];
            // B pairs read directly as packed 64-bit lanes (32B-aligned)
            ulonglong2 bu0 = *(const ulonglong2*)&Bs[k][tx * 8];
            ulonglong2 bu1 = *(const ulonglong2*)&Bs[k][tx * 8 + 4];
            u64 b2[4] = {bu0.x, bu0.y, bu1.x, bu1.y};
            u64 a2[8];
#pragma unroll
            for (int i = 0; i < 8; i++) a2[i] = dup2(a[i]);
#pragma unroll
            for (int i = 0; i < 8; i++)
#pragma unroll
                for (int j = 0; j < 4; j++)
                    ffma2(acc2[i][j], a2[i], b2[j]);
        }
        __syncthreads();
    }

    // unpack packed accumulators
    float acc[8][8];
#pragma unroll
    for (int i = 0; i < 8; i++)
#pragma unroll
        for (int j = 0; j < 4; j++)
            unpack2(acc2[i][j], acc[i][2 * j], acc[i][2 * j + 1]);

    // ---------------- epilogues ----------------
    if (MODE == EM_NONE || MODE == EM_YKV) {
#pragma unroll
        for (int i = 0; i < 8; i++) {
            long base = (long)(row0 + ty * 8 + i) * ldc + col0 + tx * 8;
            *(float4*)(C + base)     = make_float4(acc[i][0], acc[i][1], acc[i][2], acc[i][3]);
            *(float4*)(C + base + 4) = make_float4(acc[i][4], acc[i][5], acc[i][6], acc[i][7]);
        }
    } else if (MODE == EM_MASK) {
#pragma unroll
        for (int i = 0; i < 8; i++) {
            int t = row0 + ty * 8 + i;
            float v[8];
#pragma unroll
            for (int j = 0; j < 8; j++) {
                int s = col0 + tx * 8 + j;
                v[j] = (t > s) ? acc[i][j] : 0.f;
            }
            long base = (long)t * ldc + col0 + tx * 8;
            *(float4*)(C + base)     = make_float4(v[0], v[1], v[2], v[3]);
            *(float4*)(C + base + 4) = make_float4(v[4], v[5], v[6], v[7]);
        }
    } else if (MODE == EM_RELU_ROPE) {
        // C = x_sparse (relu), also write QR = rope(x_sparse) to g_qr (+ z stride)
        float* Q = g_qr + (long)z * ((long)TT * NN);
        float fr[4];
#pragma unroll
        for (int p = 0; p < 4; p++) {
            int n0 = col0 + tx * 8 + p * 2;  // even; q = (n//2)*2 == n0 for the pair
            float a = (float)exp2(-(double)n0 / 512.0);  // THETA^{-q/N}, THETA=2^16
            fr[p] = a / TWO_PI_F;
        }
#pragma unroll
        for (int i = 0; i < 8; i++) {
            int t = row0 + ty * 8 + i;
            float v[8];
#pragma unroll
            for (int j = 0; j < 8; j++) v[j] = fmaxf(acc[i][j], 0.f);
            long base = (long)t * ldc + col0 + tx * 8;
            *(float4*)(C + base)     = make_float4(v[0], v[1], v[2], v[3]);
            *(float4*)(C + base + 4) = make_float4(v[4], v[5], v[6], v[7]);
            float q[8];
#pragma unroll
            for (int p = 0; p < 4; p++) {
                float ph   = (float)t * fr[p];
                float frac = ph - floorf(ph);
                float ang  = frac * TWO_PI_F;
                float si, co;
                sincosf(ang, &si, &co);
                q[2 * p]     = v[2 * p] * co - v[2 * p + 1] * si;
                q[2 * p + 1] = v[2 * p + 1] * co + v[2 * p] * si;
            }
            *(float4*)(Q + base)     = make_float4(q[0], q[1], q[2], q[3]);
            *(float4*)(Q + base + 4) = make_float4(q[4], q[5], q[6], q[7]);
        }
    } else if (MODE == EM_RELU_MULXY) {
        // C = xy laid out [t, h*N+n]; acc = yKV@encoder_v pre-relu; multiply by x_sparse
        const float* xsrc = g_xs + (long)z * ((long)TT * NN);
#pragma unroll
        for (int i = 0; i < 8; i++) {
            int t = row0 + ty * 8 + i;
            long sbase = (long)t * NN + col0 + tx * 8;
            float4 x0 = *(const float4*)(xsrc + sbase);
            float4 x1 = *(const float4*)(xsrc + sbase + 4);
            float4 o0, o1;
            o0.x = fmaxf(acc[i][0], 0.f) * x0.x;
            o0.y = fmaxf(acc[i][1], 0.f) * x0.y;
            o0.z = fmaxf(acc[i][2], 0.f) * x0.z;
            o0.w = fmaxf(acc[i][3], 0.f) * x0.w;
            o1.x = fmaxf(acc[i][4], 0.f) * x1.x;
            o1.y = fmaxf(acc[i][5], 0.f) * x1.y;
            o1.z = fmaxf(acc[i][6], 0.f) * x1.z;
            o1.w = fmaxf(acc[i][7], 0.f) * x1.w;
            long obase = (long)t * ldc + col0 + tx * 8;  // C already offset by z*NN
            *(float4*)(C + obase)     = o0;
            *(float4*)(C + obase + 4) = o1;
        }
    }
}

// ---------------- embedding gather + LayerNorm ----------------
__global__ void embed_ln_kernel(const int* __restrict__ idx,
                                const float* __restrict__ embed)
{
    __shared__ float sb[8];
    int t = blockIdx.x, d = threadIdx.x;
    float v   = embed[idx[t] * DD + d];
    float mu  = blk_sum(v, sb) * (1.f / DD);
    float dv  = v - mu;
    float var = blk_sum(dv * dv, sb) * (1.f / DD);
    g_x[t * DD + d] = dv / sqrtf(var + LNEPS);
}

// ---------------- in-place row LayerNorm (D=256) ----------------
__global__ void ln_rows_kernel(float* __restrict__ buf)
{
    __shared__ float sb[8];
    long r = blockIdx.x;
    int  d = threadIdx.x;
    float v   = buf[r * DD + d];
    float mu  = blk_sum(v, sb) * (1.f / DD);
    float dv  = v - mu;
    float var = blk_sum(dv * dv, sb) * (1.f / DD);
    buf[r * DD + d] = dv / sqrtf(var + LNEPS);
}

// ---------------- split-K reduce + ln(yMLP), x = ln(x + ln(yMLP)) ----------
__global__ void mlp_finish_kernel()
{
    __shared__ float sb[8];
    int t = blockIdx.x, d = threadIdx.x;
    float s = 0.f;
#pragma unroll
    for (int kz = 0; kz < SPLITK; kz++)
        s += g_part[(size_t)kz * TT * DD + t * DD + d];

    float mu  = blk_sum(s, sb) * (1.f / DD);
    float dv  = s - mu;
    float var = blk_sum(dv * dv, sb) * (1.f / DD);
    float a   = dv / sqrtf(var + LNEPS);

    float b = g_x[t * DD + d] + a;
    mu  = blk_sum(b, sb) * (1.f / DD);
    dv  = b - mu;
    var = blk_sum(dv * dv, sb) * (1.f / DD);
    g_x[t * DD + d] = dv / sqrtf(var + LNEPS);
}

// ---------------- launch ----------------
extern "C" void kernel_launch(void* const* d_in, const int* in_sizes, int n_in,
                              void* d_out, int out_size)
{
    (void)in_sizes; (void)n_in; (void)out_size;
    const int*   idx       = (const int*)d_in[0];
    const float* embed     = (const float*)d_in[1];
    const float* encoder   = (const float*)d_in[2];
    const float* encoder_v = (const float*)d_in[3];
    const float* decoder   = (const float*)d_in[4];
    const float* lm_head   = (const float*)d_in[5];
    float*       out       = (float*)d_out;

    float *x, *xs, *qr, *scores, *ykv, *part;
    cudaGetSymbolAddress((void**)&x,      g_x);
    cudaGetSymbolAddress((void**)&xs,     g_xs);
    cudaGetSymbolAddress((void**)&qr,     g_qr);
    cudaGetSymbolAddress((void**)&scores, g_scores);
    cudaGetSymbolAddress((void**)&ykv,    g_ykv);
    cudaGetSymbolAddress((void**)&part,   g_part);

    embed_ln_kernel<<<TT, 256>>>(idx, embed);

    for (int l = 0; l < 2; l++) {
        // x_sparse[h] = relu(x @ encoder[h]); QR = rope(x_sparse)
        sgemm_kernel<0, EM_RELU_ROPE><<<dim3(NN / 128, TT / 128, NHH), 256>>>(
            x, encoder, xs, DD, DD, NN, NN,
            0L, (long)DD * NN, (long)TT * NN);

        // scores[h] = mask .* (QR @ QR^T)
        sgemm_kernel<1, EM_MASK><<<dim3(TT / 128, TT / 128, NHH), 256>>>(
            qr, qr, scores, NN, NN, NN, TT,
            (long)TT * NN, (long)TT * NN, (long)TT * TT);

        // yKV[h] = scores @ x   (K loop bounded by causal structure)
        sgemm_kernel<0, EM_YKV><<<dim3(DD / 128, TT / 128, NHH), 256>>>(
            scores, x, ykv, TT, TT, DD, DD,
            (long)TT * TT, 0L, (long)TT * DD);

        // LayerNorm yKV rows
        ln_rows_kernel<<<NHH * TT, 256>>>(ykv);

        // xy[t, h*N+n] = relu(yKV @ encoder_v[h]) * x_sparse   (into qr buffer)
        sgemm_kernel<0, EM_RELU_MULXY><<<dim3(NN / 128, TT / 128, NHH), 256>>>(
            ykv, encoder_v, qr, DD, DD, NN, NHH * NN,
            (long)TT * DD, (long)DD * NN, (long)NN);

        // yMLP partials = xy @ decoder  (split-K over 8 chunks of 4096)
        sgemm_kernel<0, EM_NONE><<<dim3(DD / 128, TT / 128, SPLITK), 256>>>(
            qr, decoder, part, KSPL, NHH * NN, DD, DD,
            (long)KSPL, (long)KSPL * DD, (long)TT * DD);

        // x = ln(x + ln(sum(partials)))
        mlp_finish_kernel<<<TT, 256>>>();
    }

    // logits = x @ lm_head
    sgemm_kernel<0, EM_NONE><<<dim3(VOC / 128, TT / 128, 1), 256>>>(
        x, lm_head, out, DD, DD, VOC, VOC, 0L, 0L, 0L);
}

// round 6
// speedup vs baseline: 1.7454x; 1.6864x over previous
#include <cuda_runtime.h>
#include <math.h>
#include <stdint.h>

// ---------------- problem constants ----------------
#define NHH   4
#define DD    256
#define NN    8192
#define TT    2048
#define VOC   256
#define SPLITK 8
#define KSPL  4096
#define LNEPS 1e-5f
#define TWO_PI_F 6.28318530717958647692f

// ---------------- scratch (static device globals) ----
__device__ float g_x[TT * DD];
__device__ float g_xs[(size_t)NHH * TT * NN];            // x_sparse (fp32)
__device__ float g_xy[(size_t)NHH * TT * NN];            // xy buffer
__device__ float g_scores[(size_t)NHH * TT * TT];
__device__ float g_ykv[(size_t)NHH * TT * DD];
__device__ float g_part[(size_t)SPLITK * TT * DD];
__device__ unsigned short g_qrh[(size_t)NHH * TT * NN];  // QR hi (bf16 bits)
__device__ unsigned short g_qrl[(size_t)NHH * TT * NN];  // QR lo (bf16 bits)

enum { EM_NONE = 0, EM_YKV = 2, EM_RELU_ROPE = 3, EM_RELU_MULXY = 4 };

typedef unsigned long long u64;

// ---------------- packed f32x2 helpers ----------------
__device__ __forceinline__ void ffma2(u64& d, u64 a, u64 b) {
    asm("fma.rn.f32x2 %0, %1, %2, %0;" : "+l"(d) : "l"(a), "l"(b));
}
__device__ __forceinline__ u64 dup2(float x) {
    u64 r;
    asm("mov.b64 %0, {%1, %1};" : "=l"(r) : "r"(__float_as_uint(x)));
    return r;
}
__device__ __forceinline__ void unpack2(u64 v, float& lo, float& hi) {
    unsigned a, b;
    asm("mov.b64 {%0, %1}, %2;" : "=r"(a), "=r"(b) : "l"(v));
    lo = __uint_as_float(a); hi = __uint_as_float(b);
}

// ---------------- bf16 bit helpers ----------------
__device__ __forceinline__ unsigned short f2bf(float x) {
    unsigned u = __float_as_uint(x);
    unsigned r = (u + 0x7FFFu + ((u >> 16) & 1u)) >> 16;
    return (unsigned short)r;
}

// ---------------- warp-MMA helpers (baseline sm_80+ ISA) ----------------
__device__ __forceinline__ uint32_t smem_to_u32(const void* smem_ptr) {
    uint32_t addr;
    asm("{ .reg .u64 tmp; cvta.to.shared.u64 tmp, %1; cvt.u32.u64 %0, tmp; }"
        : "=r"(addr) : "l"(smem_ptr));
    return addr;
}
__device__ __forceinline__ void ldsm4(uint32_t* r, uint32_t addr) {
    asm volatile("ldmatrix.sync.aligned.m8n8.x4.shared.b16 {%0,%1,%2,%3}, [%4];"
        : "=r"(r[0]), "=r"(r[1]), "=r"(r[2]), "=r"(r[3]) : "r"(addr));
}
__device__ __forceinline__ void mma16816(float* c, const uint32_t* a, const uint32_t* b) {
    asm volatile(
        "mma.sync.aligned.m16n8k16.row.col.f32.bf16.bf16.f32 "
        "{%0,%1,%2,%3}, {%4,%5,%6,%7}, {%8,%9}, {%0,%1,%2,%3};"
        : "+f"(c[0]), "+f"(c[1]), "+f"(c[2]), "+f"(c[3])
        : "r"(a[0]), "r"(a[1]), "r"(a[2]), "r"(a[3]), "r"(b[0]), "r"(b[1]));
}
#define CP_ASYNC16(dst, src) \
    asm volatile("cp.async.cg.shared.global [%0], [%1], 16;" :: "r"(dst), "l"(src))
#define CP_COMMIT() asm volatile("cp.async.commit_group;" ::: "memory")
#define CP_WAIT(n)  asm volatile("cp.async.wait_group %0;" :: "n"(n) : "memory")

__device__ __forceinline__ uint32_t sw128(uint32_t b) { return b ^ ((b >> 3) & 0x70); }

// ================= HMMA scores kernel =================
// scores[h] = mask .* (QR @ QR^T); QR = hi + lo (bf16 splits)
// acc = hi*hi^T + hi*lo^T + lo*hi^T in fp32.
// CTA tile 128x128, 8 warps (warp tile 32x64), K-chunk 64, cp.async double buffer.
#define HTILE 16384              // 128 rows x 128B
#define HSTG  (4 * HTILE)        // Ah, Al, Bh, Bl
#define HSMEM (2 * HSTG + 1024)

__global__ void __launch_bounds__(256)
scores_hmma(const unsigned short* __restrict__ qh,
            const unsigned short* __restrict__ ql,
            float* __restrict__ scores)
{
    const int br = blockIdx.y;
    const int bc = blockIdx.x;
    const int h  = blockIdx.z;
    if (bc > br) return;  // strictly-upper tiles never read downstream

    extern __shared__ char dsm[];
    const int tid  = threadIdx.x;
    const int wid  = tid >> 5;
    const int lane = tid & 31;
    const int wr   = wid & 3;    // warp row (4 x 32 rows)
    const int wc   = wid >> 2;   // warp col (2 x 64 cols)
    const int row0 = br * 128;
    const int col0 = bc * 128;

    const uint32_t raw = smem_to_u32(dsm);
    const uint32_t sb  = (raw + 1023u) & ~1023u;

    const size_t hb = (size_t)h * TT * NN;
    const unsigned short* srcs[4];
    srcs[0] = qh + hb + (size_t)row0 * NN;   // A hi
    srcs[1] = ql + hb + (size_t)row0 * NN;   // A lo
    srcs[2] = qh + hb + (size_t)col0 * NN;   // B hi
    srcs[3] = ql + hb + (size_t)col0 * NN;   // B lo

    float acc[2][8][4];
#pragma unroll
    for (int mi = 0; mi < 2; mi++)
#pragma unroll
        for (int ni = 0; ni < 8; ni++)
#pragma unroll
            for (int q = 0; q < 4; q++) acc[mi][ni][q] = 0.f;

    const int NITER = NN / 64;  // 128

    // issue loads for one stage via cp.async (16 x 16B per thread)
    auto load_stage = [&](int st, int kc0) {
        const uint32_t stg = sb + st * HSTG;
#pragma unroll
        for (int t4 = 0; t4 < 4; t4++) {
            const unsigned short* src = srcs[t4] + kc0;
            const uint32_t tb = stg + t4 * HTILE;
#pragma unroll
            for (int i = 0; i < 4; i++) {
                int idx = i * 256 + tid;
                int r = idx >> 3;
                int c = idx & 7;
                uint32_t dst = tb + sw128(r * 128 + c * 16);
                CP_ASYNC16(dst, src + (size_t)r * NN + c * 8);
            }
        }
    };

    load_stage(0, 0);
    CP_COMMIT();

    for (int it = 0; it < NITER; it++) {
        if (it + 1 < NITER) {
            load_stage((it + 1) & 1, (it + 1) * 64);
            CP_COMMIT();
            CP_WAIT(1);
        } else {
            CP_WAIT(0);
        }
        __syncthreads();

        const uint32_t stg = sb + (it & 1) * HSTG;
#pragma unroll
        for (int ks = 0; ks < 4; ks++) {
            const int lrow  = lane & 15;
            const int chunk = ks * 2 + (lane >> 4);

            uint32_t ah[2][4], al[2][4];
#pragma unroll
            for (int mi = 0; mi < 2; mi++) {
                int row = wr * 32 + mi * 16 + lrow;
                uint32_t off = sw128(row * 128 + chunk * 16);
                ldsm4(ah[mi], stg + 0 * HTILE + off);
                ldsm4(al[mi], stg + 1 * HTILE + off);
            }

            uint32_t bh[8][2], bl[8][2];
#pragma unroll
            for (int ng = 0; ng < 4; ng++) {
                int row = wc * 64 + ng * 16 + lrow;
                uint32_t off = sw128(row * 128 + chunk * 16);
                uint32_t t0[4], t1[4];
                ldsm4(t0, stg + 2 * HTILE + off);
                ldsm4(t1, stg + 3 * HTILE + off);
                bh[2 * ng][0] = t0[0]; bh[2 * ng][1] = t0[2];
                bh[2 * ng + 1][0] = t0[1]; bh[2 * ng + 1][1] = t0[3];
                bl[2 * ng][0] = t1[0]; bl[2 * ng][1] = t1[2];
                bl[2 * ng + 1][0] = t1[1]; bl[2 * ng + 1][1] = t1[3];
            }

#pragma unroll
            for (int mi = 0; mi < 2; mi++)
#pragma unroll
                for (int ni = 0; ni < 8; ni++) {
                    mma16816(acc[mi][ni], ah[mi], bh[ni]);
                    mma16816(acc[mi][ni], ah[mi], bl[ni]);
                    mma16816(acc[mi][ni], al[mi], bh[ni]);
                }
        }
        __syncthreads();
    }

    // epilogue: strictly-lower mask, fp32 store
    float* dst = scores + (size_t)h * TT * TT;
    const int rb = row0 + wr * 32;
    const int cb = col0 + wc * 64;
#pragma unroll
    for (int mi = 0; mi < 2; mi++) {
#pragma unroll
        for (int ni = 0; ni < 8; ni++) {
            int r = rb + mi * 16 + (lane >> 2);
            int s = cb + ni * 8 + (lane & 3) * 2;
            float2 v0, v1;
            v0.x = (r > s)     ? acc[mi][ni][0] : 0.f;
            v0.y = (r > s + 1) ? acc[mi][ni][1] : 0.f;
            v1.x = (r + 8 > s)     ? acc[mi][ni][2] : 0.f;
            v1.y = (r + 8 > s + 1) ? acc[mi][ni][3] : 0.f;
            *(float2*)(dst + (size_t)r * TT + s)       = v0;
            *(float2*)(dst + (size_t)(r + 8) * TT + s) = v1;
        }
    }
}

// ---------------- block reduction over 256 threads ----------------
__device__ __forceinline__ float blk_sum(float v, float* sb) {
    int tid = threadIdx.x;
#pragma unroll
    for (int o = 16; o > 0; o >>= 1) v += __shfl_down_sync(0xffffffffu, v, o);
    if ((tid & 31) == 0) sb[tid >> 5] = v;
    __syncthreads();
    if (tid < 32) {
        float w = (tid < 8) ? sb[tid] : 0.f;
#pragma unroll
        for (int o = 4; o > 0; o >>= 1) w += __shfl_down_sync(0xffffffffu, w, o);
        if (tid == 0) sb[0] = w;
    }
    __syncthreads();
    float r = sb[0];
    __syncthreads();
    return r;
}

// ---------------- generic 128x128x8 fp32 SGEMM with fused epilogues --------
template <int MODE>
__global__ void __launch_bounds__(256)
sgemm_kernel(const float* __restrict__ A, const float* __restrict__ B,
             float* __restrict__ C, int K,
             int lda, int ldb, int ldc,
             long offAz, long offBz, long offCz)
{
    const int z = blockIdx.z;
    A += (long)z * offAz;
    B += (long)z * offBz;
    C += (long)z * offCz;

    const int br = blockIdx.y, bc = blockIdx.x;
    const int row0 = br * 128, col0 = bc * 128;
    const int tid = threadIdx.x;
    const int tx = tid & 15, ty = tid >> 4;

    int Keff = K;
    if (MODE == EM_YKV) Keff = row0 + 128;  // scores[t,s]==0 for s>=t

    __shared__ __align__(16) float As[8][132];
    __shared__ __align__(16) float Bs[8][132];

    u64 acc2[8][4];
#pragma unroll
    for (int i = 0; i < 8; i++) {
#pragma unroll
        for (int j = 0; j < 4; j++) acc2[i][j] = 0ull;
    }

    const int ar = tid >> 1;
    const int ak = (tid & 1) * 4;
    const int bkr = tid >> 5;
    const int bcc = (tid & 31) * 4;

    const float* Ap = A + (long)(row0 + ar) * lda + ak;
    const float* Bp = B + (long)bkr * ldb + col0 + bcc;

    float4 a4 = *(const float4*)Ap;  Ap += 8;
    float4 b4 = *(const float4*)Bp;  Bp += (long)8 * ldb;

    for (int k0 = 0; k0 < Keff; k0 += 8) {
        As[ak + 0][ar] = a4.x; As[ak + 1][ar] = a4.y;
        As[ak + 2][ar] = a4.z; As[ak + 3][ar] = a4.w;
        Bs[bkr][bcc + 0] = b4.x; Bs[bkr][bcc + 1] = b4.y;
        Bs[bkr][bcc + 2] = b4.z; Bs[bkr][bcc + 3] = b4.w;
        __syncthreads();

        if (k0 + 8 < Keff) {
            a4 = *(const float4*)Ap;  Ap += 8;
            b4 = *(const float4*)Bp;  Bp += (long)8 * ldb;
        }

#pragma unroll
        for (int k = 0; k < 8; k++) {
            float a[8];
            *(float4*)&a[0] = *(const float4*)&As[k][ty * 8];
            *(float4*)&a[4] = *(const float4*)&As[k][ty * 8 + 4];
            ulonglong2 bu0 = *(const ulonglong2*)&Bs[k][tx * 8];
            ulonglong2 bu1 = *(const ulonglong2*)&Bs[k][tx * 8 + 4];
            u64 b2[4];
            b2[0] = bu0.x; b2[1] = bu0.y; b2[2] = bu1.x; b2[3] = bu1.y;
            u64 a2[8];
#pragma unroll
            for (int i = 0; i < 8; i++) a2[i] = dup2(a[i]);
#pragma unroll
            for (int i = 0; i < 8; i++) {
#pragma unroll
                for (int j = 0; j < 4; j++) ffma2(acc2[i][j], a2[i], b2[j]);
            }
        }
        __syncthreads();
    }

    float acc[8][8];
#pragma unroll
    for (int i = 0; i < 8; i++) {
#pragma unroll
        for (int j = 0; j < 4; j++) unpack2(acc2[i][j], acc[i][2 * j], acc[i][2 * j + 1]);
    }

    if (MODE == EM_NONE || MODE == EM_YKV) {
#pragma unroll
        for (int i = 0; i < 8; i++) {
            long base = (long)(row0 + ty * 8 + i) * ldc + col0 + tx * 8;
            *(float4*)(C + base)     = make_float4(acc[i][0], acc[i][1], acc[i][2], acc[i][3]);
            *(float4*)(C + base + 4) = make_float4(acc[i][4], acc[i][5], acc[i][6], acc[i][7]);
        }
    } else if (MODE == EM_RELU_ROPE) {
        // C = x_sparse (relu); write bf16 hi/lo split of QR for the HMMA scores GEMM
        unsigned short* Qh = g_qrh + (size_t)z * ((size_t)TT * NN);
        unsigned short* Ql = g_qrl + (size_t)z * ((size_t)TT * NN);
        float fr[4];
#pragma unroll
        for (int p = 0; p < 4; p++) {
            int n0 = col0 + tx * 8 + p * 2;
            float a = (float)exp2(-(double)n0 / 512.0);
            fr[p] = a / TWO_PI_F;
        }
#pragma unroll
        for (int i = 0; i < 8; i++) {
            int t = row0 + ty * 8 + i;
            float v[8];
#pragma unroll
            for (int j = 0; j < 8; j++) v[j] = fmaxf(acc[i][j], 0.f);
            long base = (long)t * ldc + col0 + tx * 8;
            *(float4*)(C + base)     = make_float4(v[0], v[1], v[2], v[3]);
            *(float4*)(C + base + 4) = make_float4(v[4], v[5], v[6], v[7]);
            float q[8];
#pragma unroll
            for (int p = 0; p < 4; p++) {
                float ph   = (float)t * fr[p];
                float frac = ph - floorf(ph);
                float ang  = frac * TWO_PI_F;
                float si, co;
                sincosf(ang, &si, &co);
                q[2 * p]     = v[2 * p] * co - v[2 * p + 1] * si;
                q[2 * p + 1] = v[2 * p + 1] * co + v[2 * p] * si;
            }
            unsigned short h8[8];
            unsigned short l8[8];
#pragma unroll
            for (int j = 0; j < 8; j++) {
                unsigned short hh = f2bf(q[j]);
                float rem = q[j] - __uint_as_float((unsigned)hh << 16);
                h8[j] = hh;
                l8[j] = f2bf(rem);
            }
            *(uint4*)(Qh + base) = *(uint4*)h8;
            *(uint4*)(Ql + base) = *(uint4*)l8;
        }
    } else if (MODE == EM_RELU_MULXY) {
        const float* xsrc = g_xs + (size_t)z * ((size_t)TT * NN);
#pragma unroll
        for (int i = 0; i < 8; i++) {
            int t = row0 + ty * 8 + i;
            long sbase = (long)t * NN + col0 + tx * 8;
            float4 x0 = *(const float4*)(xsrc + sbase);
            float4 x1 = *(const float4*)(xsrc + sbase + 4);
            float4 o0, o1;
            o0.x = fmaxf(acc[i][0], 0.f) * x0.x;
            o0.y = fmaxf(acc[i][1], 0.f) * x0.y;
            o0.z = fmaxf(acc[i][2], 0.f) * x0.z;
            o0.w = fmaxf(acc[i][3], 0.f) * x0.w;
            o1.x = fmaxf(acc[i][4], 0.f) * x1.x;
            o1.y = fmaxf(acc[i][5], 0.f) * x1.y;
            o1.z = fmaxf(acc[i][6], 0.f) * x1.z;
            o1.w = fmaxf(acc[i][7], 0.f) * x1.w;
            long obase = (long)t * ldc + col0 + tx * 8;
            *(float4*)(C + obase)     = o0;
            *(float4*)(C + obase + 4) = o1;
        }
    }
}

// ---------------- small elementwise kernels ----------------
__global__ void embed_ln_kernel(const int* __restrict__ idx,
                                const float* __restrict__ embed)
{
    __shared__ float sb[8];
    int t = blockIdx.x, d = threadIdx.x;
    float v   = embed[idx[t] * DD + d];
    float mu  = blk_sum(v, sb) * (1.f / DD);
    float dv  = v - mu;
    float var = blk_sum(dv * dv, sb) * (1.f / DD);
    g_x[t * DD + d] = dv / sqrtf(var + LNEPS);
}

__global__ void ln_rows_kernel(float* __restrict__ buf)
{
    __shared__ float sb[8];
    long r = blockIdx.x;
    int  d = threadIdx.x;
    float v   = buf[r * DD + d];
    float mu  = blk_sum(v, sb) * (1.f / DD);
    float dv  = v - mu;
    float var = blk_sum(dv * dv, sb) * (1.f / DD);
    buf[r * DD + d] = dv / sqrtf(var + LNEPS);
}

__global__ void mlp_finish_kernel()
{
    __shared__ float sb[8];
    int t = blockIdx.x, d = threadIdx.x;
    float s = 0.f;
#pragma unroll
    for (int kz = 0; kz < SPLITK; kz++)
        s += g_part[(size_t)kz * TT * DD + t * DD + d];

    float mu  = blk_sum(s, sb) * (1.f / DD);
    float dv  = s - mu;
    float var = blk_sum(dv * dv, sb) * (1.f / DD);
    float a   = dv / sqrtf(var + LNEPS);

    float b = g_x[t * DD + d] + a;
    mu  = blk_sum(b, sb) * (1.f / DD);
    dv  = b - mu;
    var = blk_sum(dv * dv, sb) * (1.f / DD);
    g_x[t * DD + d] = dv / sqrtf(var + LNEPS);
}

// ---------------- launch ----------------
extern "C" void kernel_launch(void* const* d_in, const int* in_sizes, int n_in,
                              void* d_out, int out_size)
{
    (void)in_sizes; (void)n_in; (void)out_size;
    const int*   idx       = (const int*)d_in[0];
    const float* embed     = (const float*)d_in[1];
    const float* encoder   = (const float*)d_in[2];
    const float* encoder_v = (const float*)d_in[3];
    const float* decoder   = (const float*)d_in[4];
    const float* lm_head   = (const float*)d_in[5];
    float*       out       = (float*)d_out;

    float* x      = 0;
    float* xs     = 0;
    float* xy     = 0;
    float* scores = 0;
    float* ykv    = 0;
    float* part   = 0;
    unsigned short* qrh = 0;
    unsigned short* qrl = 0;
    cudaGetSymbolAddress((void**)&x,      g_x);
    cudaGetSymbolAddress((void**)&xs,     g_xs);
    cudaGetSymbolAddress((void**)&xy,     g_xy);
    cudaGetSymbolAddress((void**)&scores, g_scores);
    cudaGetSymbolAddress((void**)&ykv,    g_ykv);
    cudaGetSymbolAddress((void**)&part,   g_part);
    cudaGetSymbolAddress((void**)&qrh,    g_qrh);
    cudaGetSymbolAddress((void**)&qrl,    g_qrl);

    cudaFuncSetAttribute(scores_hmma, cudaFuncAttributeMaxDynamicSharedMemorySize, HSMEM);

    embed_ln_kernel<<<TT, 256>>>(idx, embed);

    for (int l = 0; l < 2; l++) {
        // x_sparse[h] = relu(x @ encoder[h]); bf16 hi/lo QR written alongside
        sgemm_kernel<EM_RELU_ROPE><<<dim3(NN / 128, TT / 128, NHH), 256>>>(
            x, encoder, xs, DD, DD, NN, NN,
            0L, (long)DD * NN, (long)TT * NN);

        // scores[h] = mask .* (QR @ QR^T) — warp-level HMMA bf16 split-2
        scores_hmma<<<dim3(TT / 128, TT / 128, NHH), 256, HSMEM>>>(qrh, qrl, scores);

        // yKV[h] = scores @ x
        sgemm_kernel<EM_YKV><<<dim3(DD / 128, TT / 128, NHH), 256>>>(
            scores, x, ykv, TT, TT, DD, DD,
            (long)TT * TT, 0L, (long)TT * DD);

        ln_rows_kernel<<<NHH * TT, 256>>>(ykv);

        // xy = relu(yKV @ encoder_v) * x_sparse
        sgemm_kernel<EM_RELU_MULXY><<<dim3(NN / 128, TT / 128, NHH), 256>>>(
            ykv, encoder_v, xy, DD, DD, NN, NHH * NN,
            (long)TT * DD, (long)DD * NN, (long)NN);

        // yMLP partials = xy @ decoder (split-K)
        sgemm_kernel<EM_NONE><<<dim3(DD / 128, TT / 128, SPLITK), 256>>>(
            xy, decoder, part, KSPL, NHH * NN, DD, DD,
            (long)KSPL, (long)KSPL * DD, (long)TT * DD);

        mlp_finish_kernel<<<TT, 256>>>();
    }

    sgemm_kernel<EM_NONE><<<dim3(VOC / 128, TT / 128, 1), 256>>>(
        x, lm_head, out, DD, DD, VOC, VOC, 0L, 0L, 0L);
}

// round 7
// speedup vs baseline: 2.2438x; 1.2855x over previous
#include <cuda_runtime.h>
#include <math.h>
#include <stdint.h>

// ---------------- problem constants ----------------
#define NHH   4
#define DD    256
#define NN    8192
#define TT    2048
#define VOC   256
#define SPLITK 16
#define KSPL  2048              // NHH*NN/SPLITK
#define LNEPS 1e-5f
#define TWO_PI_F 6.28318530717958647692f

// ---------------- scratch (static device globals) ----
__device__ float g_x[TT * DD];
__device__ unsigned short g_xh[TT * DD];
__device__ unsigned short g_xl[TT * DD];
__device__ float g_xs[(size_t)NHH * TT * NN];
__device__ float g_scores[(size_t)NHH * TT * TT];
__device__ float g_ykv[(size_t)NHH * TT * DD];
__device__ unsigned short g_ykvh[(size_t)NHH * TT * DD];
__device__ unsigned short g_ykvl[(size_t)NHH * TT * DD];
__device__ float g_part[(size_t)SPLITK * TT * DD];
__device__ unsigned short g_qrh[(size_t)NHH * TT * NN];
__device__ unsigned short g_qrl[(size_t)NHH * TT * NN];
__device__ unsigned short g_xyh[(size_t)NHH * TT * NN];
__device__ unsigned short g_xyl[(size_t)NHH * TT * NN];
__device__ unsigned short g_ench[(size_t)NHH * DD * NN];
__device__ unsigned short g_encl[(size_t)NHH * DD * NN];
__device__ unsigned short g_encvh[(size_t)NHH * DD * NN];
__device__ unsigned short g_encvl[(size_t)NHH * DD * NN];
__device__ unsigned short g_dech[(size_t)NHH * NN * DD];
__device__ unsigned short g_decl[(size_t)NHH * NN * DD];

enum { EM_NONE = 0, EM_YKV = 2 };
enum { HM_NONE = 0, HM_ROPE = 1, HM_MULXY = 2 };

typedef unsigned long long u64;

// ---------------- packed f32x2 helpers ----------------
__device__ __forceinline__ void ffma2(u64& d, u64 a, u64 b) {
    asm("fma.rn.f32x2 %0, %1, %2, %0;" : "+l"(d) : "l"(a), "l"(b));
}
__device__ __forceinline__ u64 dup2(float x) {
    u64 r;
    asm("mov.b64 %0, {%1, %1};" : "=l"(r) : "r"(__float_as_uint(x)));
    return r;
}
__device__ __forceinline__ void unpack2(u64 v, float& lo, float& hi) {
    unsigned a, b;
    asm("mov.b64 {%0, %1}, %2;" : "=r"(a), "=r"(b) : "l"(v));
    lo = __uint_as_float(a); hi = __uint_as_float(b);
}

// ---------------- bf16 bit helpers ----------------
__device__ __forceinline__ unsigned short f2bf(float x) {
    unsigned u = __float_as_uint(x);
    unsigned r = (u + 0x7FFFu + ((u >> 16) & 1u)) >> 16;
    return (unsigned short)r;
}
__device__ __forceinline__ float bf2f(unsigned short b) {
    return __uint_as_float((unsigned)b << 16);
}

// ---------------- warp-MMA helpers ----------------
__device__ __forceinline__ uint32_t smem_to_u32(const void* smem_ptr) {
    uint32_t addr;
    asm("{ .reg .u64 tmp; cvta.to.shared.u64 tmp, %1; cvt.u32.u64 %0, tmp; }"
        : "=r"(addr) : "l"(smem_ptr));
    return addr;
}
__device__ __forceinline__ void ldsm4(uint32_t* r, uint32_t addr) {
    asm volatile("ldmatrix.sync.aligned.m8n8.x4.shared.b16 {%0,%1,%2,%3}, [%4];"
        : "=r"(r[0]), "=r"(r[1]), "=r"(r[2]), "=r"(r[3]) : "r"(addr));
}
__device__ __forceinline__ void ldsm4t(uint32_t* r, uint32_t addr) {
    asm volatile("ldmatrix.sync.aligned.m8n8.x4.trans.shared.b16 {%0,%1,%2,%3}, [%4];"
        : "=r"(r[0]), "=r"(r[1]), "=r"(r[2]), "=r"(r[3]) : "r"(addr));
}
__device__ __forceinline__ void mma16816(float* c, const uint32_t* a, const uint32_t* b) {
    asm volatile(
        "mma.sync.aligned.m16n8k16.row.col.f32.bf16.bf16.f32 "
        "{%0,%1,%2,%3}, {%4,%5,%6,%7}, {%8,%9}, {%0,%1,%2,%3};"
        : "+f"(c[0]), "+f"(c[1]), "+f"(c[2]), "+f"(c[3])
        : "r"(a[0]), "r"(a[1]), "r"(a[2]), "r"(a[3]), "r"(b[0]), "r"(b[1]));
}
#define CP_ASYNC16(dst, src) \
    asm volatile("cp.async.cg.shared.global [%0], [%1], 16;" :: "r"(dst), "l"(src))
#define CP_COMMIT() asm volatile("cp.async.commit_group;" ::: "memory")
#define CP_WAIT(n)  asm volatile("cp.async.wait_group %0;" :: "n"(n) : "memory")

__device__ __forceinline__ uint32_t sw128(uint32_t b) { return b ^ ((b >> 3) & 0x70); }
__device__ __forceinline__ uint32_t sw256(uint32_t b) { return b ^ ((b >> 4) & 0x70); }

#define HTILE 16384
#define HSTG  (4 * HTILE)
#define HSMEM (2 * HSTG + 1024)

// ================= HMMA scores kernel (unchanged from R6) =================
__global__ void __launch_bounds__(256)
scores_hmma(const unsigned short* __restrict__ qh,
            const unsigned short* __restrict__ ql,
            float* __restrict__ scores)
{
    const int br = blockIdx.y;
    const int bc = blockIdx.x;
    const int h  = blockIdx.z;
    if (bc > br) return;

    extern __shared__ char dsm[];
    const int tid  = threadIdx.x;
    const int wid  = tid >> 5;
    const int lane = tid & 31;
    const int wr   = wid & 3;
    const int wc   = wid >> 2;
    const int row0 = br * 128;
    const int col0 = bc * 128;

    const uint32_t raw = smem_to_u32(dsm);
    const uint32_t sb  = (raw + 1023u) & ~1023u;

    const size_t hb = (size_t)h * TT * NN;
    const unsigned short* srcs[4];
    srcs[0] = qh + hb + (size_t)row0 * NN;
    srcs[1] = ql + hb + (size_t)row0 * NN;
    srcs[2] = qh + hb + (size_t)col0 * NN;
    srcs[3] = ql + hb + (size_t)col0 * NN;

    float acc[2][8][4];
#pragma unroll
    for (int mi = 0; mi < 2; mi++)
#pragma unroll
        for (int ni = 0; ni < 8; ni++)
#pragma unroll
            for (int q = 0; q < 4; q++) acc[mi][ni][q] = 0.f;

    const int NITER = NN / 64;

    auto load_stage = [&](int st, int kc0) {
        const uint32_t stg = sb + st * HSTG;
#pragma unroll
        for (int t4 = 0; t4 < 4; t4++) {
            const unsigned short* src = srcs[t4] + kc0;
            const uint32_t tb = stg + t4 * HTILE;
#pragma unroll
            for (int i = 0; i < 4; i++) {
                int idx = i * 256 + tid;
                int r = idx >> 3;
                int c = idx & 7;
                uint32_t dst = tb + sw128(r * 128 + c * 16);
                CP_ASYNC16(dst, src + (size_t)r * NN + c * 8);
            }
        }
    };

    load_stage(0, 0);
    CP_COMMIT();

    for (int it = 0; it < NITER; it++) {
        if (it + 1 < NITER) {
            load_stage((it + 1) & 1, (it + 1) * 64);
            CP_COMMIT();
            CP_WAIT(1);
        } else {
            CP_WAIT(0);
        }
        __syncthreads();

        const uint32_t stg = sb + (it & 1) * HSTG;
#pragma unroll
        for (int ks = 0; ks < 4; ks++) {
            const int lrow  = lane & 15;
            const int chunk = ks * 2 + (lane >> 4);

            uint32_t ah[2][4], al[2][4];
#pragma unroll
            for (int mi = 0; mi < 2; mi++) {
                int row = wr * 32 + mi * 16 + lrow;
                uint32_t off = sw128(row * 128 + chunk * 16);
                ldsm4(ah[mi], stg + 0 * HTILE + off);
                ldsm4(al[mi], stg + 1 * HTILE + off);
            }

            uint32_t bh[8][2], bl[8][2];
#pragma unroll
            for (int ng = 0; ng < 4; ng++) {
                int row = wc * 64 + ng * 16 + lrow;
                uint32_t off = sw128(row * 128 + chunk * 16);
                uint32_t t0[4], t1[4];
                ldsm4(t0, stg + 2 * HTILE + off);
                ldsm4(t1, stg + 3 * HTILE + off);
                bh[2 * ng][0] = t0[0]; bh[2 * ng][1] = t0[2];
                bh[2 * ng + 1][0] = t0[1]; bh[2 * ng + 1][1] = t0[3];
                bl[2 * ng][0] = t1[0]; bl[2 * ng][1] = t1[2];
                bl[2 * ng + 1][0] = t1[1]; bl[2 * ng + 1][1] = t1[3];
            }

#pragma unroll
            for (int mi = 0; mi < 2; mi++)
#pragma unroll
                for (int ni = 0; ni < 8; ni++) {
                    mma16816(acc[mi][ni], ah[mi], bh[ni]);
                    mma16816(acc[mi][ni], ah[mi], bl[ni]);
                    mma16816(acc[mi][ni], al[mi], bh[ni]);
                }
        }
        __syncthreads();
    }

    float* dst = scores + (size_t)h * TT * TT;
    const int rb = row0 + wr * 32;
    const int cb = col0 + wc * 64;
#pragma unroll
    for (int mi = 0; mi < 2; mi++) {
#pragma unroll
        for (int ni = 0; ni < 8; ni++) {
            int r = rb + mi * 16 + (lane >> 2);
            int s = cb + ni * 8 + (lane & 3) * 2;
            float2 v0, v1;
            v0.x = (r > s)     ? acc[mi][ni][0] : 0.f;
            v0.y = (r > s + 1) ? acc[mi][ni][1] : 0.f;
            v1.x = (r + 8 > s)     ? acc[mi][ni][2] : 0.f;
            v1.y = (r + 8 > s + 1) ? acc[mi][ni][3] : 0.f;
            *(float2*)(dst + (size_t)r * TT + s)       = v0;
            *(float2*)(dst + (size_t)(r + 8) * TT + s) = v1;
        }
    }
}

// ================= generic HMMA GEMM: C = A*B, A [M,K] k-contig, B [K,N] n-contig
// A,B in bf16 hi/lo split; acc = Ah*Bh + Ah*Bl + Al*Bh (fp32).
// CTA 128x128, 8 warps (32x64 each), K-chunk 64, cp.async double buffer.
// B staged [k][n] (256B rows, sw256), fragments via ldmatrix.trans.
template <int HM>
__global__ void __launch_bounds__(256)
hmma_gemm(const unsigned short* __restrict__ Ah, const unsigned short* __restrict__ Al,
          const unsigned short* __restrict__ Bh, const unsigned short* __restrict__ Bl,
          float* __restrict__ C, int K, int lda, int ldb, int ldc,
          long offAz, long offBz, long offCz)
{
    const int z = blockIdx.z;
    Ah += (long)z * offAz;
    Al += (long)z * offAz;
    Bh += (long)z * offBz;
    Bl += (long)z * offBz;
    if (HM != HM_MULXY) C += (long)z * offCz;

    extern __shared__ char dsm[];
    const int tid  = threadIdx.x;
    const int wid  = tid >> 5;
    const int lane = tid & 31;
    const int wr   = wid & 3;
    const int wc   = wid >> 2;
    const int row0 = blockIdx.y * 128;
    const int col0 = blockIdx.x * 128;

    const uint32_t raw = smem_to_u32(dsm);
    const uint32_t sb  = (raw + 1023u) & ~1023u;

    const unsigned short* A0 = Ah + (size_t)row0 * lda;
    const unsigned short* A1 = Al + (size_t)row0 * lda;

    float acc[2][8][4];
#pragma unroll
    for (int mi = 0; mi < 2; mi++)
#pragma unroll
        for (int ni = 0; ni < 8; ni++)
#pragma unroll
            for (int q = 0; q < 4; q++) acc[mi][ni][q] = 0.f;

    const int NITER = K / 64;

    auto load_stage = [&](int st, int k0) {
        const uint32_t stg = sb + st * HSTG;
#pragma unroll
        for (int i = 0; i < 4; i++) {
            int idx = i * 256 + tid;
            int r = idx >> 3;
            int c = idx & 7;
            uint32_t off = sw128(r * 128 + c * 16);
            CP_ASYNC16(stg + 0 * HTILE + off, A0 + (size_t)r * lda + k0 + c * 8);
            CP_ASYNC16(stg + 1 * HTILE + off, A1 + (size_t)r * lda + k0 + c * 8);
        }
#pragma unroll
        for (int i = 0; i < 4; i++) {
            int idx = i * 256 + tid;
            int r = idx >> 4;
            int c = idx & 15;
            uint32_t off = sw256(r * 256 + c * 16);
            CP_ASYNC16(stg + 2 * HTILE + off, Bh + (size_t)(k0 + r) * ldb + col0 + c * 8);
            CP_ASYNC16(stg + 3 * HTILE + off, Bl + (size_t)(k0 + r) * ldb + col0 + c * 8);
        }
    };

    load_stage(0, 0);
    CP_COMMIT();

    for (int it = 0; it < NITER; it++) {
        if (it + 1 < NITER) {
            load_stage((it + 1) & 1, (it + 1) * 64);
            CP_COMMIT();
            CP_WAIT(1);
        } else {
            CP_WAIT(0);
        }
        __syncthreads();

        const uint32_t stg = sb + (it & 1) * HSTG;
#pragma unroll
        for (int ks = 0; ks < 4; ks++) {
            const int lrow = lane & 15;

            uint32_t ah[2][4], al[2][4];
#pragma unroll
            for (int mi = 0; mi < 2; mi++) {
                int row = wr * 32 + mi * 16 + lrow;
                uint32_t off = sw128(row * 128 + (ks * 2 + (lane >> 4)) * 16);
                ldsm4(ah[mi], stg + 0 * HTILE + off);
                ldsm4(al[mi], stg + 1 * HTILE + off);
            }

            uint32_t bh[8][2], bl[8][2];
#pragma unroll
            for (int ng = 0; ng < 4; ng++) {
                int kk = ks * 16 + lrow;
                int nc = wc * 64 + ng * 16 + (lane >> 4) * 8;
                uint32_t off = sw256(kk * 256 + nc * 2);
                uint32_t t0[4], t1[4];
                ldsm4t(t0, stg + 2 * HTILE + off);
                ldsm4t(t1, stg + 3 * HTILE + off);
                bh[2 * ng][0] = t0[0]; bh[2 * ng][1] = t0[1];
                bh[2 * ng + 1][0] = t0[2]; bh[2 * ng + 1][1] = t0[3];
                bl[2 * ng][0] = t1[0]; bl[2 * ng][1] = t1[1];
                bl[2 * ng + 1][0] = t1[2]; bl[2 * ng + 1][1] = t1[3];
            }

#pragma unroll
            for (int mi = 0; mi < 2; mi++)
#pragma unroll
                for (int ni = 0; ni < 8; ni++) {
                    mma16816(acc[mi][ni], ah[mi], bh[ni]);
                    mma16816(acc[mi][ni], ah[mi], bl[ni]);
                    mma16816(acc[mi][ni], al[mi], bh[ni]);
                }
        }
        __syncthreads();
    }

    // ---------------- epilogues ----------------
    const int rb = row0 + wr * 32;
    const int cb = col0 + wc * 64;

    if (HM == HM_NONE) {
#pragma unroll
        for (int mi = 0; mi < 2; mi++) {
#pragma unroll
            for (int ni = 0; ni < 8; ni++) {
                int r = rb + mi * 16 + (lane >> 2);
                int s = cb + ni * 8 + (lane & 3) * 2;
                *(float2*)(C + (size_t)r * ldc + s) =
                    make_float2(acc[mi][ni][0], acc[mi][ni][1]);
                *(float2*)(C + (size_t)(r + 8) * ldc + s) =
                    make_float2(acc[mi][ni][2], acc[mi][ni][3]);
            }
        }
    } else if (HM == HM_ROPE) {
        unsigned short* Qh = g_qrh + (size_t)z * TT * NN;
        unsigned short* Ql = g_qrl + (size_t)z * TT * NN;
#pragma unroll
        for (int ni = 0; ni < 8; ni++) {
            int n0 = cb + ni * 8 + (lane & 3) * 2;
            float fr = (float)exp2(-(double)n0 / 512.0) / TWO_PI_F;
#pragma unroll
            for (int mi = 0; mi < 2; mi++) {
                int rbase = rb + mi * 16 + (lane >> 2);
#pragma unroll
                for (int half = 0; half < 2; half++) {
                    int r = rbase + half * 8;
                    float v0 = fmaxf(acc[mi][ni][half * 2 + 0], 0.f);
                    float v1 = fmaxf(acc[mi][ni][half * 2 + 1], 0.f);
                    *(float2*)(C + (size_t)r * ldc + n0) = make_float2(v0, v1);
                    float ph   = (float)r * fr;
                    float frac = ph - floorf(ph);
                    float ang  = frac * TWO_PI_F;
                    float si, co;
                    sincosf(ang, &si, &co);
                    float q0 = v0 * co - v1 * si;
                    float q1 = v1 * co + v0 * si;
                    unsigned short h0 = f2bf(q0);
                    unsigned short h1 = f2bf(q1);
                    unsigned short l0 = f2bf(q0 - bf2f(h0));
                    unsigned short l1 = f2bf(q1 - bf2f(h1));
                    unsigned hv = (unsigned)h0 | ((unsigned)h1 << 16);
                    unsigned lv = (unsigned)l0 | ((unsigned)l1 << 16);
                    *(unsigned*)(Qh + (size_t)r * NN + n0) = hv;
                    *(unsigned*)(Ql + (size_t)r * NN + n0) = lv;
                }
            }
        }
    } else if (HM == HM_MULXY) {
        const float* xsrc = g_xs + (size_t)z * TT * NN;
        unsigned short* Xh = g_xyh;
        unsigned short* Xl = g_xyl;
        const int colz = z * NN;
#pragma unroll
        for (int mi = 0; mi < 2; mi++) {
#pragma unroll
            for (int ni = 0; ni < 8; ni++) {
                int n0 = cb + ni * 8 + (lane & 3) * 2;
                int rbase = rb + mi * 16 + (lane >> 2);
#pragma unroll
                for (int half = 0; half < 2; half++) {
                    int r = rbase + half * 8;
                    float2 xv = *(const float2*)(xsrc + (size_t)r * NN + n0);
                    float v0 = fmaxf(acc[mi][ni][half * 2 + 0], 0.f) * xv.x;
                    float v1 = fmaxf(acc[mi][ni][half * 2 + 1], 0.f) * xv.y;
                    unsigned short h0 = f2bf(v0);
                    unsigned short h1 = f2bf(v1);
                    unsigned short l0 = f2bf(v0 - bf2f(h0));
                    unsigned short l1 = f2bf(v1 - bf2f(h1));
                    size_t base = (size_t)r * (NHH * NN) + colz + n0;
                    *(unsigned*)(Xh + base) = (unsigned)h0 | ((unsigned)h1 << 16);
                    *(unsigned*)(Xl + base) = (unsigned)l0 | ((unsigned)l1 << 16);
                }
            }
        }
    }
}

// ---------------- weight split conversion ----------------
__global__ void cvt_split(const float* __restrict__ src,
                          unsigned short* __restrict__ h,
                          unsigned short* __restrict__ l, long n)
{
    long i = ((long)blockIdx.x * blockDim.x + threadIdx.x) * 4;
    if (i >= n) return;
    float4 v = *(const float4*)(src + i);
    unsigned short h0 = f2bf(v.x), h1 = f2bf(v.y), h2 = f2bf(v.z), h3 = f2bf(v.w);
    unsigned short l0 = f2bf(v.x - bf2f(h0)), l1 = f2bf(v.y - bf2f(h1));
    unsigned short l2 = f2bf(v.z - bf2f(h2)), l3 = f2bf(v.w - bf2f(h3));
    uint2 hv, lv;
    hv.x = (unsigned)h0 | ((unsigned)h1 << 16);
    hv.y = (unsigned)h2 | ((unsigned)h3 << 16);
    lv.x = (unsigned)l0 | ((unsigned)l1 << 16);
    lv.y = (unsigned)l2 | ((unsigned)l3 << 16);
    *(uint2*)(h + i) = hv;
    *(uint2*)(l + i) = lv;
}

// ---------------- block reduction over 256 threads ----------------
__device__ __forceinline__ float blk_sum(float v, float* sb) {
    int tid = threadIdx.x;
#pragma unroll
    for (int o = 16; o > 0; o >>= 1) v += __shfl_down_sync(0xffffffffu, v, o);
    if ((tid & 31) == 0) sb[tid >> 5] = v;
    __syncthreads();
    if (tid < 32) {
        float w = (tid < 8) ? sb[tid] : 0.f;
#pragma unroll
        for (int o = 4; o > 0; o >>= 1) w += __shfl_down_sync(0xffffffffu, w, o);
        if (tid == 0) sb[0] = w;
    }
    __syncthreads();
    float r = sb[0];
    __syncthreads();
    return r;
}

// ---------------- fp32 SGEMM (kept for YKV + lm_head) ----------------
template <int MODE>
__global__ void __launch_bounds__(256)
sgemm_kernel(const float* __restrict__ A, const float* __restrict__ B,
             float* __restrict__ C, int K,
             int lda, int ldb, int ldc,
             long offAz, long offBz, long offCz)
{
    const int z = blockIdx.z;
    A += (long)z * offAz;
    B += (long)z * offBz;
    C += (long)z * offCz;

    const int br = blockIdx.y, bc = blockIdx.x;
    const int row0 = br * 128, col0 = bc * 128;
    const int tid = threadIdx.x;
    const int tx = tid & 15, ty = tid >> 4;

    int Keff = K;
    if (MODE == EM_YKV) Keff = row0 + 128;

    __shared__ __align__(16) float As[8][132];
    __shared__ __align__(16) float Bs[8][132];

    u64 acc2[8][4];
#pragma unroll
    for (int i = 0; i < 8; i++) {
#pragma unroll
        for (int j = 0; j < 4; j++) acc2[i][j] = 0ull;
    }

    const int ar = tid >> 1;
    const int ak = (tid & 1) * 4;
    const int bkr = tid >> 5;
    const int bcc = (tid & 31) * 4;

    const float* Ap = A + (long)(row0 + ar) * lda + ak;
    const float* Bp = B + (long)bkr * ldb + col0 + bcc;

    float4 a4 = *(const float4*)Ap;  Ap += 8;
    float4 b4 = *(const float4*)Bp;  Bp += (long)8 * ldb;

    for (int k0 = 0; k0 < Keff; k0 += 8) {
        As[ak + 0][ar] = a4.x; As[ak + 1][ar] = a4.y;
        As[ak + 2][ar] = a4.z; As[ak + 3][ar] = a4.w;
        Bs[bkr][bcc + 0] = b4.x; Bs[bkr][bcc + 1] = b4.y;
        Bs[bkr][bcc + 2] = b4.z; Bs[bkr][bcc + 3] = b4.w;
        __syncthreads();

        if (k0 + 8 < Keff) {
            a4 = *(const float4*)Ap;  Ap += 8;
            b4 = *(const float4*)Bp;  Bp += (long)8 * ldb;
        }

#pragma unroll
        for (int k = 0; k < 8; k++) {
            float a[8];
            *(float4*)&a[0] = *(const float4*)&As[k][ty * 8];
            *(float4*)&a[4] = *(const float4*)&As[k][ty * 8 + 4];
            ulonglong2 bu0 = *(const ulonglong2*)&Bs[k][tx * 8];
            ulonglong2 bu1 = *(const ulonglong2*)&Bs[k][tx * 8 + 4];
            u64 b2[4];
            b2[0] = bu0.x; b2[1] = bu0.y; b2[2] = bu1.x; b2[3] = bu1.y;
            u64 a2[8];
#pragma unroll
            for (int i = 0; i < 8; i++) a2[i] = dup2(a[i]);
#pragma unroll
            for (int i = 0; i < 8; i++) {
#pragma unroll
                for (int j = 0; j < 4; j++) ffma2(acc2[i][j], a2[i], b2[j]);
            }
        }
        __syncthreads();
    }

    float acc[8][8];
#pragma unroll
    for (int i = 0; i < 8; i++) {
#pragma unroll
        for (int j = 0; j < 4; j++) unpack2(acc2[i][j], acc[i][2 * j], acc[i][2 * j + 1]);
    }

#pragma unroll
    for (int i = 0; i < 8; i++) {
        long base = (long)(row0 + ty * 8 + i) * ldc + col0 + tx * 8;
        *(float4*)(C + base)     = make_float4(acc[i][0], acc[i][1], acc[i][2], acc[i][3]);
        *(float4*)(C + base + 4) = make_float4(acc[i][4], acc[i][5], acc[i][6], acc[i][7]);
    }
}

// ---------------- small elementwise kernels ----------------
__global__ void embed_ln_kernel(const int* __restrict__ idx,
                                const float* __restrict__ embed)
{
    __shared__ float sb[8];
    int t = blockIdx.x, d = threadIdx.x;
    float v   = embed[idx[t] * DD + d];
    float mu  = blk_sum(v, sb) * (1.f / DD);
    float dv  = v - mu;
    float var = blk_sum(dv * dv, sb) * (1.f / DD);
    float o = dv / sqrtf(var + LNEPS);
    g_x[t * DD + d] = o;
    unsigned short hh = f2bf(o);
    g_xh[t * DD + d] = hh;
    g_xl[t * DD + d] = f2bf(o - bf2f(hh));
}

__global__ void ln_rows_kernel(float* __restrict__ buf)
{
    __shared__ float sb[8];
    long r = blockIdx.x;
    int  d = threadIdx.x;
    float v   = buf[r * DD + d];
    float mu  = blk_sum(v, sb) * (1.f / DD);
    float dv  = v - mu;
    float var = blk_sum(dv * dv, sb) * (1.f / DD);
    float o = dv / sqrtf(var + LNEPS);
    buf[r * DD + d] = o;
    unsigned short hh = f2bf(o);
    g_ykvh[r * DD + d] = hh;
    g_ykvl[r * DD + d] = f2bf(o - bf2f(hh));
}

__global__ void mlp_finish_kernel()
{
    __shared__ float sb[8];
    int t = blockIdx.x, d = threadIdx.x;
    float s = 0.f;
#pragma unroll
    for (int kz = 0; kz < SPLITK; kz++)
        s += g_part[(size_t)kz * TT * DD + t * DD + d];

    float mu  = blk_sum(s, sb) * (1.f / DD);
    float dv  = s - mu;
    float var = blk_sum(dv * dv, sb) * (1.f / DD);
    float a   = dv / sqrtf(var + LNEPS);

    float b = g_x[t * DD + d] + a;
    mu  = blk_sum(b, sb) * (1.f / DD);
    dv  = b - mu;
    var = blk_sum(dv * dv, sb) * (1.f / DD);
    float o = dv / sqrtf(var + LNEPS);
    g_x[t * DD + d] = o;
    unsigned short hh = f2bf(o);
    g_xh[t * DD + d] = hh;
    g_xl[t * DD + d] = f2bf(o - bf2f(hh));
}

// ---------------- launch ----------------
extern "C" void kernel_launch(void* const* d_in, const int* in_sizes, int n_in,
                              void* d_out, int out_size)
{
    (void)in_sizes; (void)n_in; (void)out_size;
    const int*   idx       = (const int*)d_in[0];
    const float* embed     = (const float*)d_in[1];
    const float* encoder   = (const float*)d_in[2];
    const float* encoder_v = (const float*)d_in[3];
    const float* decoder   = (const float*)d_in[4];
    const float* lm_head   = (const float*)d_in[5];
    float*       out       = (float*)d_out;

    float* x = 0; float* xs = 0; float* scores = 0; float* ykv = 0; float* part = 0;
    unsigned short *qrh = 0, *qrl = 0, *xyh = 0, *xyl = 0;
    unsigned short *xh = 0, *xl = 0, *ykvh = 0, *ykvl = 0;
    unsigned short *ench = 0, *encl = 0, *encvh = 0, *encvl = 0, *dech = 0, *decl = 0;
    cudaGetSymbolAddress((void**)&x,      g_x);
    cudaGetSymbolAddress((void**)&xs,     g_xs);
    cudaGetSymbolAddress((void**)&scores, g_scores);
    cudaGetSymbolAddress((void**)&ykv,    g_ykv);
    cudaGetSymbolAddress((void**)&part,   g_part);
    cudaGetSymbolAddress((void**)&qrh,    g_qrh);
    cudaGetSymbolAddress((void**)&qrl,    g_qrl);
    cudaGetSymbolAddress((void**)&xyh,    g_xyh);
    cudaGetSymbolAddress((void**)&xyl,    g_xyl);
    cudaGetSymbolAddress((void**)&xh,     g_xh);
    cudaGetSymbolAddress((void**)&xl,     g_xl);
    cudaGetSymbolAddress((void**)&ykvh,   g_ykvh);
    cudaGetSymbolAddress((void**)&ykvl,   g_ykvl);
    cudaGetSymbolAddress((void**)&ench,   g_ench);
    cudaGetSymbolAddress((void**)&encl,   g_encl);
    cudaGetSymbolAddress((void**)&encvh,  g_encvh);
    cudaGetSymbolAddress((void**)&encvl,  g_encvl);
    cudaGetSymbolAddress((void**)&dech,   g_dech);
    cudaGetSymbolAddress((void**)&decl,   g_decl);

    cudaFuncSetAttribute(scores_hmma, cudaFuncAttributeMaxDynamicSharedMemorySize, HSMEM);
    cudaFuncSetAttribute(hmma_gemm<HM_NONE>,  cudaFuncAttributeMaxDynamicSharedMemorySize, HSMEM);
    cudaFuncSetAttribute(hmma_gemm<HM_ROPE>,  cudaFuncAttributeMaxDynamicSharedMemorySize, HSMEM);
    cudaFuncSetAttribute(hmma_gemm<HM_MULXY>, cudaFuncAttributeMaxDynamicSharedMemorySize, HSMEM);

    const long WN = (long)NHH * DD * NN;  // weight elems
    cvt_split<<<(int)(WN / 4 / 256), 256>>>(encoder,   ench,  encl,  WN);
    cvt_split<<<(int)(WN / 4 / 256), 256>>>(encoder_v, encvh, encvl, WN);
    cvt_split<<<(int)(WN / 4 / 256), 256>>>(decoder,   dech,  decl,  WN);

    embed_ln_kernel<<<TT, 256>>>(idx, embed);

    for (int l = 0; l < 2; l++) {
        // x_sparse = relu(x @ encoder) fp32 to g_xs; QR hi/lo to g_qrh/l
        hmma_gemm<HM_ROPE><<<dim3(NN / 128, TT / 128, NHH), 256, HSMEM>>>(
            xh, xl, ench, encl, xs, DD, DD, NN, NN,
            0L, (long)DD * NN, (long)TT * NN);

        // scores = mask .* (QR @ QR^T)
        scores_hmma<<<dim3(TT / 128, TT / 128, NHH), 256, HSMEM>>>(qrh, qrl, scores);

        // yKV = scores @ x (fp32, causal-K-bounded)
        sgemm_kernel<EM_YKV><<<dim3(DD / 128, TT / 128, NHH), 256>>>(
            scores, x, ykv, TT, TT, DD, DD,
            (long)TT * TT, 0L, (long)TT * DD);

        ln_rows_kernel<<<NHH * TT, 256>>>(ykv);

        // xy = relu(yKV @ encoder_v) * x_sparse  -> bf16 hi/lo
        hmma_gemm<HM_MULXY><<<dim3(NN / 128, TT / 128, NHH), 256, HSMEM>>>(
            ykvh, ykvl, encvh, encvl, xs, DD, DD, NN, 0,
            (long)TT * DD, (long)DD * NN, 0L);

        // yMLP partials = xy @ decoder (split-K 16)
        hmma_gemm<HM_NONE><<<dim3(DD / 128, TT / 128, SPLITK), 256, HSMEM>>>(
            xyh, xyl, dech, decl, part, KSPL, NHH * NN, DD, DD,
            (long)KSPL, (long)KSPL * DD, (long)TT * DD);

        mlp_finish_kernel<<<TT, 256>>>();
    }

    sgemm_kernel<EM_NONE><<<dim3(VOC / 128, TT / 128, 1), 256>>>(
        x, lm_head, out, DD, DD, VOC, VOC, 0L, 0L, 0L);
}

// round 8
// speedup vs baseline: 2.3576x; 1.0507x over previous
#include <cuda_runtime.h>
#include <math.h>
#include <stdint.h>

// ---------------- problem constants ----------------
#define NHH   4
#define DD    256
#define NN    8192
#define TT    2048
#define VOC   256
#define SPLITK 16
#define KSPL  2048              // NHH*NN/SPLITK
#define LNEPS 1e-5f
#define TWO_PI_F 6.28318530717958647692f

// ---------------- scratch (static device globals) ----
__device__ float g_x[TT * DD];
__device__ unsigned short g_xh[TT * DD];
__device__ unsigned short g_xl[TT * DD];
__device__ float g_xs[(size_t)NHH * TT * NN];
__device__ unsigned short g_sch[(size_t)NHH * TT * TT];   // scores hi (bf16)
__device__ unsigned short g_scl[(size_t)NHH * TT * TT];   // scores lo (bf16)
__device__ float g_ykv[(size_t)NHH * TT * DD];
__device__ unsigned short g_ykvh[(size_t)NHH * TT * DD];
__device__ unsigned short g_ykvl[(size_t)NHH * TT * DD];
__device__ float g_part[(size_t)SPLITK * TT * DD];
__device__ unsigned short g_qrh[(size_t)NHH * TT * NN];
__device__ unsigned short g_qrl[(size_t)NHH * TT * NN];
__device__ unsigned short g_xyh[(size_t)NHH * TT * NN];
__device__ unsigned short g_xyl[(size_t)NHH * TT * NN];
__device__ unsigned short g_ench[(size_t)NHH * DD * NN];
__device__ unsigned short g_encl[(size_t)NHH * DD * NN];
__device__ unsigned short g_encvh[(size_t)NHH * DD * NN];
__device__ unsigned short g_encvl[(size_t)NHH * DD * NN];
__device__ unsigned short g_dech[(size_t)NHH * NN * DD];
__device__ unsigned short g_decl[(size_t)NHH * NN * DD];

enum { EM_NONE = 0 };
enum { HM_NONE = 0, HM_ROPE = 1, HM_MULXY = 2 };

typedef unsigned long long u64;

// ---------------- packed f32x2 helpers ----------------
__device__ __forceinline__ void ffma2(u64& d, u64 a, u64 b) {
    asm("fma.rn.f32x2 %0, %1, %2, %0;" : "+l"(d) : "l"(a), "l"(b));
}
__device__ __forceinline__ u64 dup2(float x) {
    u64 r;
    asm("mov.b64 %0, {%1, %1};" : "=l"(r) : "r"(__float_as_uint(x)));
    return r;
}
__device__ __forceinline__ void unpack2(u64 v, float& lo, float& hi) {
    unsigned a, b;
    asm("mov.b64 {%0, %1}, %2;" : "=r"(a), "=r"(b) : "l"(v));
    lo = __uint_as_float(a); hi = __uint_as_float(b);
}

// ---------------- bf16 bit helpers ----------------
__device__ __forceinline__ unsigned short f2bf(float x) {
    unsigned u = __float_as_uint(x);
    unsigned r = (u + 0x7FFFu + ((u >> 16) & 1u)) >> 16;
    return (unsigned short)r;
}
__device__ __forceinline__ float bf2f(unsigned short b) {
    return __uint_as_float((unsigned)b << 16);
}
__device__ __forceinline__ unsigned pack_hl(float a, float b,
                                            unsigned short& la, unsigned short& lb) {
    unsigned short ha = f2bf(a), hb = f2bf(b);
    la = f2bf(a - bf2f(ha));
    lb = f2bf(b - bf2f(hb));
    return (unsigned)ha | ((unsigned)hb << 16);
}

// ---------------- warp-MMA helpers ----------------
__device__ __forceinline__ uint32_t smem_to_u32(const void* smem_ptr) {
    uint32_t addr;
    asm("{ .reg .u64 tmp; cvta.to.shared.u64 tmp, %1; cvt.u32.u64 %0, tmp; }"
        : "=r"(addr) : "l"(smem_ptr));
    return addr;
}
__device__ __forceinline__ void ldsm4(uint32_t* r, uint32_t addr) {
    asm volatile("ldmatrix.sync.aligned.m8n8.x4.shared.b16 {%0,%1,%2,%3}, [%4];"
        : "=r"(r[0]), "=r"(r[1]), "=r"(r[2]), "=r"(r[3]) : "r"(addr));
}
__device__ __forceinline__ void ldsm4t(uint32_t* r, uint32_t addr) {
    asm volatile("ldmatrix.sync.aligned.m8n8.x4.trans.shared.b16 {%0,%1,%2,%3}, [%4];"
        : "=r"(r[0]), "=r"(r[1]), "=r"(r[2]), "=r"(r[3]) : "r"(addr));
}
__device__ __forceinline__ void mma16816(float* c, const uint32_t* a, const uint32_t* b) {
    asm volatile(
        "mma.sync.aligned.m16n8k16.row.col.f32.bf16.bf16.f32 "
        "{%0,%1,%2,%3}, {%4,%5,%6,%7}, {%8,%9}, {%0,%1,%2,%3};"
        : "+f"(c[0]), "+f"(c[1]), "+f"(c[2]), "+f"(c[3])
        : "r"(a[0]), "r"(a[1]), "r"(a[2]), "r"(a[3]), "r"(b[0]), "r"(b[1]));
}
#define CP_ASYNC16(dst, src) \
    asm volatile("cp.async.cg.shared.global [%0], [%1], 16;" :: "r"(dst), "l"(src))
#define CP_COMMIT() asm volatile("cp.async.commit_group;" ::: "memory")
#define CP_WAIT(n)  asm volatile("cp.async.wait_group %0;" :: "n"(n) : "memory")

__device__ __forceinline__ uint32_t sw128(uint32_t b) { return b ^ ((b >> 3) & 0x70); }
__device__ __forceinline__ uint32_t sw256(uint32_t b) { return b ^ ((b >> 4) & 0x70); }

#define HTILE 16384
#define HSTG  (4 * HTILE)
#define NSTG  3
#define HSMEM (NSTG * HSTG + 1024)

// ================= HMMA scores kernel (3-stage pipeline, bf16 hi/lo out) ========
__global__ void __launch_bounds__(256)
scores_hmma(const unsigned short* __restrict__ qh,
            const unsigned short* __restrict__ ql,
            unsigned short* __restrict__ sch,
            unsigned short* __restrict__ scl)
{
    const int br = blockIdx.y;
    const int bc = blockIdx.x;
    const int h  = blockIdx.z;
    if (bc > br) return;

    extern __shared__ char dsm[];
    const int tid  = threadIdx.x;
    const int wid  = tid >> 5;
    const int lane = tid & 31;
    const int wr   = wid & 3;
    const int wc   = wid >> 2;
    const int row0 = br * 128;
    const int col0 = bc * 128;

    const uint32_t raw = smem_to_u32(dsm);
    const uint32_t sb  = (raw + 1023u) & ~1023u;

    const size_t hb = (size_t)h * TT * NN;
    const unsigned short* srcs[4];
    srcs[0] = qh + hb + (size_t)row0 * NN;
    srcs[1] = ql + hb + (size_t)row0 * NN;
    srcs[2] = qh + hb + (size_t)col0 * NN;
    srcs[3] = ql + hb + (size_t)col0 * NN;

    float acc[2][8][4];
#pragma unroll
    for (int mi = 0; mi < 2; mi++)
#pragma unroll
        for (int ni = 0; ni < 8; ni++)
#pragma unroll
            for (int q = 0; q < 4; q++) acc[mi][ni][q] = 0.f;

    const int NITER = NN / 64;

    auto load_stage = [&](int st, int kc0) {
        const uint32_t stg = sb + st * HSTG;
#pragma unroll
        for (int t4 = 0; t4 < 4; t4++) {
            const unsigned short* src = srcs[t4] + kc0;
            const uint32_t tb = stg + t4 * HTILE;
#pragma unroll
            for (int i = 0; i < 4; i++) {
                int idx = i * 256 + tid;
                int r = idx >> 3;
                int c = idx & 7;
                uint32_t dst = tb + sw128(r * 128 + c * 16);
                CP_ASYNC16(dst, src + (size_t)r * NN + c * 8);
            }
        }
    };

    load_stage(0, 0);
    CP_COMMIT();
    load_stage(1, 64);
    CP_COMMIT();

    for (int it = 0; it < NITER; it++) {
        if (it + 2 < NITER) {
            load_stage((it + 2) % NSTG, (it + 2) * 64);
            CP_COMMIT();
            CP_WAIT(2);
        } else {
            CP_WAIT(0);
        }
        __syncthreads();

        const uint32_t stg = sb + (it % NSTG) * HSTG;
#pragma unroll
        for (int ks = 0; ks < 4; ks++) {
            const int lrow  = lane & 15;
            const int chunk = ks * 2 + (lane >> 4);

            uint32_t ah[2][4], al[2][4];
#pragma unroll
            for (int mi = 0; mi < 2; mi++) {
                int row = wr * 32 + mi * 16 + lrow;
                uint32_t off = sw128(row * 128 + chunk * 16);
                ldsm4(ah[mi], stg + 0 * HTILE + off);
                ldsm4(al[mi], stg + 1 * HTILE + off);
            }

            uint32_t bh[8][2], bl[8][2];
#pragma unroll
            for (int ng = 0; ng < 4; ng++) {
                int row = wc * 64 + ng * 16 + lrow;
                uint32_t off = sw128(row * 128 + chunk * 16);
                uint32_t t0[4], t1[4];
                ldsm4(t0, stg + 2 * HTILE + off);
                ldsm4(t1, stg + 3 * HTILE + off);
                bh[2 * ng][0] = t0[0]; bh[2 * ng][1] = t0[2];
                bh[2 * ng + 1][0] = t0[1]; bh[2 * ng + 1][1] = t0[3];
                bl[2 * ng][0] = t1[0]; bl[2 * ng][1] = t1[2];
                bl[2 * ng + 1][0] = t1[1]; bl[2 * ng + 1][1] = t1[3];
            }

#pragma unroll
            for (int mi = 0; mi < 2; mi++)
#pragma unroll
                for (int ni = 0; ni < 8; ni++) {
                    mma16816(acc[mi][ni], ah[mi], bh[ni]);
                    mma16816(acc[mi][ni], ah[mi], bl[ni]);
                    mma16816(acc[mi][ni], al[mi], bh[ni]);
                }
        }
        __syncthreads();
    }

    // epilogue: strictly-lower mask, write bf16 hi/lo split
    unsigned short* dh = sch + (size_t)h * TT * TT;
    unsigned short* dl = scl + (size_t)h * TT * TT;
    const int rb = row0 + wr * 32;
    const int cb = col0 + wc * 64;
#pragma unroll
    for (int mi = 0; mi < 2; mi++) {
#pragma unroll
        for (int ni = 0; ni < 8; ni++) {
            int r = rb + mi * 16 + (lane >> 2);
            int s = cb + ni * 8 + (lane & 3) * 2;
#pragma unroll
            for (int half = 0; half < 2; half++) {
                int rr = r + half * 8;
                float v0 = (rr > s)     ? acc[mi][ni][half * 2 + 0] : 0.f;
                float v1 = (rr > s + 1) ? acc[mi][ni][half * 2 + 1] : 0.f;
                unsigned short l0, l1;
                unsigned hv = pack_hl(v0, v1, l0, l1);
                size_t base = (size_t)rr * TT + s;
                *(unsigned*)(dh + base) = hv;
                *(unsigned*)(dl + base) = (unsigned)l0 | ((unsigned)l1 << 16);
            }
        }
    }
}

// ================= generic HMMA GEMM (3-stage): C = A*B =================
// A [M,K] k-contig, B [K,N] n-contig; bf16 hi/lo; acc = Ah*Bh + Ah*Bl + Al*Bh.
template <int HM, int CAUSAL>
__global__ void __launch_bounds__(256)
hmma_gemm(const unsigned short* __restrict__ Ah, const unsigned short* __restrict__ Al,
          const unsigned short* __restrict__ Bh, const unsigned short* __restrict__ Bl,
          float* __restrict__ C, int K, int lda, int ldb, int ldc,
          long offAz, long offBz, long offCz)
{
    const int z = blockIdx.z;
    Ah += (long)z * offAz;
    Al += (long)z * offAz;
    Bh += (long)z * offBz;
    Bl += (long)z * offBz;
    if (HM != HM_MULXY) C += (long)z * offCz;

    extern __shared__ char dsm[];
    const int tid  = threadIdx.x;
    const int wid  = tid >> 5;
    const int lane = tid & 31;
    const int wr   = wid & 3;
    const int wc   = wid >> 2;
    const int row0 = blockIdx.y * 128;
    const int col0 = blockIdx.x * 128;

    const uint32_t raw = smem_to_u32(dsm);
    const uint32_t sb  = (raw + 1023u) & ~1023u;

    const unsigned short* A0 = Ah + (size_t)row0 * lda;
    const unsigned short* A1 = Al + (size_t)row0 * lda;

    float acc[2][8][4];
#pragma unroll
    for (int mi = 0; mi < 2; mi++)
#pragma unroll
        for (int ni = 0; ni < 8; ni++)
#pragma unroll
            for (int q = 0; q < 4; q++) acc[mi][ni][q] = 0.f;

    const int NITER = (CAUSAL ? (row0 + 128) : K) / 64;

    auto load_stage = [&](int st, int k0) {
        const uint32_t stg = sb + st * HSTG;
#pragma unroll
        for (int i = 0; i < 4; i++) {
            int idx = i * 256 + tid;
            int r = idx >> 3;
            int c = idx & 7;
            uint32_t off = sw128(r * 128 + c * 16);
            CP_ASYNC16(stg + 0 * HTILE + off, A0 + (size_t)r * lda + k0 + c * 8);
            CP_ASYNC16(stg + 1 * HTILE + off, A1 + (size_t)r * lda + k0 + c * 8);
        }
#pragma unroll
        for (int i = 0; i < 4; i++) {
            int idx = i * 256 + tid;
            int r = idx >> 4;
            int c = idx & 15;
            uint32_t off = sw256(r * 256 + c * 16);
            CP_ASYNC16(stg + 2 * HTILE + off, Bh + (size_t)(k0 + r) * ldb + col0 + c * 8);
            CP_ASYNC16(stg + 3 * HTILE + off, Bl + (size_t)(k0 + r) * ldb + col0 + c * 8);
        }
    };

    load_stage(0, 0);
    CP_COMMIT();
    if (NITER > 1) { load_stage(1, 64); CP_COMMIT(); }

    for (int it = 0; it < NITER; it++) {
        if (it + 2 < NITER) {
            load_stage((it + 2) % NSTG, (it + 2) * 64);
            CP_COMMIT();
            CP_WAIT(2);
        } else {
            CP_WAIT(0);
        }
        __syncthreads();

        const uint32_t stg = sb + (it % NSTG) * HSTG;
#pragma unroll
        for (int ks = 0; ks < 4; ks++) {
            const int lrow = lane & 15;

            uint32_t ah[2][4], al[2][4];
#pragma unroll
            for (int mi = 0; mi < 2; mi++) {
                int row = wr * 32 + mi * 16 + lrow;
                uint32_t off = sw128(row * 128 + (ks * 2 + (lane >> 4)) * 16);
                ldsm4(ah[mi], stg + 0 * HTILE + off);
                ldsm4(al[mi], stg + 1 * HTILE + off);
            }

            uint32_t bh[8][2], bl[8][2];
#pragma unroll
            for (int ng = 0; ng < 4; ng++) {
                int kk = ks * 16 + lrow;
                int nc = wc * 64 + ng * 16 + (lane >> 4) * 8;
                uint32_t off = sw256(kk * 256 + nc * 2);
                uint32_t t0[4], t1[4];
                ldsm4t(t0, stg + 2 * HTILE + off);
                ldsm4t(t1, stg + 3 * HTILE + off);
                bh[2 * ng][0] = t0[0]; bh[2 * ng][1] = t0[1];
                bh[2 * ng + 1][0] = t0[2]; bh[2 * ng + 1][1] = t0[3];
                bl[2 * ng][0] = t1[0]; bl[2 * ng][1] = t1[1];
                bl[2 * ng + 1][0] = t1[2]; bl[2 * ng + 1][1] = t1[3];
            }

#pragma unroll
            for (int mi = 0; mi < 2; mi++)
#pragma unroll
                for (int ni = 0; ni < 8; ni++) {
                    mma16816(acc[mi][ni], ah[mi], bh[ni]);
                    mma16816(acc[mi][ni], ah[mi], bl[ni]);
                    mma16816(acc[mi][ni], al[mi], bh[ni]);
                }
        }
        __syncthreads();
    }

    // ---------------- epilogues ----------------
    const int rb = row0 + wr * 32;
    const int cb = col0 + wc * 64;

    if (HM == HM_NONE) {
#pragma unroll
        for (int mi = 0; mi < 2; mi++) {
#pragma unroll
            for (int ni = 0; ni < 8; ni++) {
                int r = rb + mi * 16 + (lane >> 2);
                int s = cb + ni * 8 + (lane & 3) * 2;
                *(float2*)(C + (size_t)r * ldc + s) =
                    make_float2(acc[mi][ni][0], acc[mi][ni][1]);
                *(float2*)(C + (size_t)(r + 8) * ldc + s) =
                    make_float2(acc[mi][ni][2], acc[mi][ni][3]);
            }
        }
    } else if (HM == HM_ROPE) {
        unsigned short* Qh = g_qrh + (size_t)z * TT * NN;
        unsigned short* Ql = g_qrl + (size_t)z * TT * NN;
#pragma unroll
        for (int ni = 0; ni < 8; ni++) {
            int n0 = cb + ni * 8 + (lane & 3) * 2;
            float fr = (float)exp2(-(double)n0 / 512.0) / TWO_PI_F;
#pragma unroll
            for (int mi = 0; mi < 2; mi++) {
                int rbase = rb + mi * 16 + (lane >> 2);
#pragma unroll
                for (int half = 0; half < 2; half++) {
                    int r = rbase + half * 8;
                    float v0 = fmaxf(acc[mi][ni][half * 2 + 0], 0.f);
                    float v1 = fmaxf(acc[mi][ni][half * 2 + 1], 0.f);
                    *(float2*)(C + (size_t)r * ldc + n0) = make_float2(v0, v1);
                    float ph   = (float)r * fr;
                    float frac = ph - floorf(ph);
                    float ang  = frac * TWO_PI_F;
                    float si, co;
                    sincosf(ang, &si, &co);
                    float q0 = v0 * co - v1 * si;
                    float q1 = v1 * co + v0 * si;
                    unsigned short l0, l1;
                    unsigned hv = pack_hl(q0, q1, l0, l1);
                    *(unsigned*)(Qh + (size_t)r * NN + n0) = hv;
                    *(unsigned*)(Ql + (size_t)r * NN + n0) = (unsigned)l0 | ((unsigned)l1 << 16);
                }
            }
        }
    } else if (HM == HM_MULXY) {
        const float* xsrc = g_xs + (size_t)z * TT * NN;
        unsigned short* Xh = g_xyh;
        unsigned short* Xl = g_xyl;
        const int colz = z * NN;
#pragma unroll
        for (int mi = 0; mi < 2; mi++) {
#pragma unroll
            for (int ni = 0; ni < 8; ni++) {
                int n0 = cb + ni * 8 + (lane & 3) * 2;
                int rbase = rb + mi * 16 + (lane >> 2);
#pragma unroll
                for (int half = 0; half < 2; half++) {
                    int r = rbase + half * 8;
                    float2 xv = *(const float2*)(xsrc + (size_t)r * NN + n0);
                    float v0 = fmaxf(acc[mi][ni][half * 2 + 0], 0.f) * xv.x;
                    float v1 = fmaxf(acc[mi][ni][half * 2 + 1], 0.f) * xv.y;
                    unsigned short l0, l1;
                    unsigned hv = pack_hl(v0, v1, l0, l1);
                    size_t base = (size_t)r * (NHH * NN) + colz + n0;
                    *(unsigned*)(Xh + base) = hv;
                    *(unsigned*)(Xl + base) = (unsigned)l0 | ((unsigned)l1 << 16);
                }
            }
        }
    }
}

// ---------------- weight split conversion ----------------
__global__ void cvt_split(const float* __restrict__ src,
                          unsigned short* __restrict__ h,
                          unsigned short* __restrict__ l, long n)
{
    long i = ((long)blockIdx.x * blockDim.x + threadIdx.x) * 4;
    if (i >= n) return;
    float4 v = *(const float4*)(src + i);
    unsigned short l0, l1, l2, l3;
    uint2 hv, lv;
    hv.x = pack_hl(v.x, v.y, l0, l1);
    hv.y = pack_hl(v.z, v.w, l2, l3);
    lv.x = (unsigned)l0 | ((unsigned)l1 << 16);
    lv.y = (unsigned)l2 | ((unsigned)l3 << 16);
    *(uint2*)(h + i) = hv;
    *(uint2*)(l + i) = lv;
}

// ---------------- block reduction over 256 threads ----------------
__device__ __forceinline__ float blk_sum(float v, float* sb) {
    int tid = threadIdx.x;
#pragma unroll
    for (int o = 16; o > 0; o >>= 1) v += __shfl_down_sync(0xffffffffu, v, o);
    if ((tid & 31) == 0) sb[tid >> 5] = v;
    __syncthreads();
    if (tid < 32) {
        float w = (tid < 8) ? sb[tid] : 0.f;
#pragma unroll
        for (int o = 4; o > 0; o >>= 1) w += __shfl_down_sync(0xffffffffu, w, o);
        if (tid == 0) sb[0] = w;
    }
    __syncthreads();
    float r = sb[0];
    __syncthreads();
    return r;
}

// ---------------- fp32 SGEMM (kept for lm_head) ----------------
template <int MODE>
__global__ void __launch_bounds__(256)
sgemm_kernel(const float* __restrict__ A, const float* __restrict__ B,
             float* __restrict__ C, int K,
             int lda, int ldb, int ldc,
             long offAz, long offBz, long offCz)
{
    const int z = blockIdx.z;
    A += (long)z * offAz;
    B += (long)z * offBz;
    C += (long)z * offCz;

    const int br = blockIdx.y, bc = blockIdx.x;
    const int row0 = br * 128, col0 = bc * 128;
    const int tid = threadIdx.x;
    const int tx = tid & 15, ty = tid >> 4;

    __shared__ __align__(16) float As[8][132];
    __shared__ __align__(16) float Bs[8][132];

    u64 acc2[8][4];
#pragma unroll
    for (int i = 0; i < 8; i++) {
#pragma unroll
        for (int j = 0; j < 4; j++) acc2[i][j] = 0ull;
    }

    const int ar = tid >> 1;
    const int ak = (tid & 1) * 4;
    const int bkr = tid >> 5;
    const int bcc = (tid & 31) * 4;

    const float* Ap = A + (long)(row0 + ar) * lda + ak;
    const float* Bp = B + (long)bkr * ldb + col0 + bcc;

    float4 a4 = *(const float4*)Ap;  Ap += 8;
    float4 b4 = *(const float4*)Bp;  Bp += (long)8 * ldb;

    for (int k0 = 0; k0 < K; k0 += 8) {
        As[ak + 0][ar] = a4.x; As[ak + 1][ar] = a4.y;
        As[ak + 2][ar] = a4.z; As[ak + 3][ar] = a4.w;
        Bs[bkr][bcc + 0] = b4.x; Bs[bkr][bcc + 1] = b4.y;
        Bs[bkr][bcc + 2] = b4.z; Bs[bkr][bcc + 3] = b4.w;
        __syncthreads();

        if (k0 + 8 < K) {
            a4 = *(const float4*)Ap;  Ap += 8;
            b4 = *(const float4*)Bp;  Bp += (long)8 * ldb;
        }

#pragma unroll
        for (int k = 0; k < 8; k++) {
            float a[8];
            *(float4*)&a[0] = *(const float4*)&As[k][ty * 8];
            *(float4*)&a[4] = *(const float4*)&As[k][ty * 8 + 4];
            ulonglong2 bu0 = *(const ulonglong2*)&Bs[k][tx * 8];
            ulonglong2 bu1 = *(const ulonglong2*)&Bs[k][tx * 8 + 4];
            u64 b2[4];
            b2[0] = bu0.x; b2[1] = bu0.y; b2[2] = bu1.x; b2[3] = bu1.y;
            u64 a2[8];
#pragma unroll
            for (int i = 0; i < 8; i++) a2[i] = dup2(a[i]);
#pragma unroll
            for (int i = 0; i < 8; i++) {
#pragma unroll
                for (int j = 0; j < 4; j++) ffma2(acc2[i][j], a2[i], b2[j]);
            }
        }
        __syncthreads();
    }

    float acc[8][8];
#pragma unroll
    for (int i = 0; i < 8; i++) {
#pragma unroll
        for (int j = 0; j < 4; j++) unpack2(acc2[i][j], acc[i][2 * j], acc[i][2 * j + 1]);
    }

#pragma unroll
    for (int i = 0; i < 8; i++) {
        long base = (long)(row0 + ty * 8 + i) * ldc + col0 + tx * 8;
        *(float4*)(C + base)     = make_float4(acc[i][0], acc[i][1], acc[i][2], acc[i][3]);
        *(float4*)(C + base + 4) = make_float4(acc[i][4], acc[i][5], acc[i][6], acc[i][7]);
    }
}

// ---------------- small elementwise kernels ----------------
__global__ void embed_ln_kernel(const int* __restrict__ idx,
                                const float* __restrict__ embed)
{
    __shared__ float sb[8];
    int t = blockIdx.x, d = threadIdx.x;
    float v   = embed[idx[t] * DD + d];
    float mu  = blk_sum(v, sb) * (1.f / DD);
    float dv  = v - mu;
    float var = blk_sum(dv * dv, sb) * (1.f / DD);
    float o = dv / sqrtf(var + LNEPS);
    g_x[t * DD + d] = o;
    unsigned short hh = f2bf(o);
    g_xh[t * DD + d] = hh;
    g_xl[t * DD + d] = f2bf(o - bf2f(hh));
}

__global__ void ln_rows_kernel(float* __restrict__ buf)
{
    __shared__ float sb[8];
    long r = blockIdx.x;
    int  d = threadIdx.x;
    float v   = buf[r * DD + d];
    float mu  = blk_sum(v, sb) * (1.f / DD);
    float dv  = v - mu;
    float var = blk_sum(dv * dv, sb) * (1.f / DD);
    float o = dv / sqrtf(var + LNEPS);
    buf[r * DD + d] = o;
    unsigned short hh = f2bf(o);
    g_ykvh[r * DD + d] = hh;
    g_ykvl[r * DD + d] = f2bf(o - bf2f(hh));
}

__global__ void mlp_finish_kernel()
{
    __shared__ float sb[8];
    int t = blockIdx.x, d = threadIdx.x;
    float s = 0.f;
#pragma unroll
    for (int kz = 0; kz < SPLITK; kz++)
        s += g_part[(size_t)kz * TT * DD + t * DD + d];

    float mu  = blk_sum(s, sb) * (1.f / DD);
    float dv  = s - mu;
    float var = blk_sum(dv * dv, sb) * (1.f / DD);
    float a   = dv / sqrtf(var + LNEPS);

    float b = g_x[t * DD + d] + a;
    mu  = blk_sum(b, sb) * (1.f / DD);
    dv  = b - mu;
    var = blk_sum(dv * dv, sb) * (1.f / DD);
    float o = dv / sqrtf(var + LNEPS);
    g_x[t * DD + d] = o;
    unsigned short hh = f2bf(o);
    g_xh[t * DD + d] = hh;
    g_xl[t * DD + d] = f2bf(o - bf2f(hh));
}

// ---------------- launch ----------------
extern "C" void kernel_launch(void* const* d_in, const int* in_sizes, int n_in,
                              void* d_out, int out_size)
{
    (void)in_sizes; (void)n_in; (void)out_size;
    const int*   idx       = (const int*)d_in[0];
    const float* embed     = (const float*)d_in[1];
    const float* encoder   = (const float*)d_in[2];
    const float* encoder_v = (const float*)d_in[3];
    const float* decoder   = (const float*)d_in[4];
    const float* lm_head   = (const float*)d_in[5];
    float*       out       = (float*)d_out;

    float* x = 0; float* xs = 0; float* ykv = 0; float* part = 0;
    unsigned short *sch = 0, *scl = 0;
    unsigned short *qrh = 0, *qrl = 0, *xyh = 0, *xyl = 0;
    unsigned short *xh = 0, *xl = 0, *ykvh = 0, *ykvl = 0;
    unsigned short *ench = 0, *encl = 0, *encvh = 0, *encvl = 0, *dech = 0, *decl = 0;
    cudaGetSymbolAddress((void**)&x,      g_x);
    cudaGetSymbolAddress((void**)&xs,     g_xs);
    cudaGetSymbolAddress((void**)&sch,    g_sch);
    cudaGetSymbolAddress((void**)&scl,    g_scl);
    cudaGetSymbolAddress((void**)&ykv,    g_ykv);
    cudaGetSymbolAddress((void**)&part,   g_part);
    cudaGetSymbolAddress((void**)&qrh,    g_qrh);
    cudaGetSymbolAddress((void**)&qrl,    g_qrl);
    cudaGetSymbolAddress((void**)&xyh,    g_xyh);
    cudaGetSymbolAddress((void**)&xyl,    g_xyl);
    cudaGetSymbolAddress((void**)&xh,     g_xh);
    cudaGetSymbolAddress((void**)&xl,     g_xl);
    cudaGetSymbolAddress((void**)&ykvh,   g_ykvh);
    cudaGetSymbolAddress((void**)&ykvl,   g_ykvl);
    cudaGetSymbolAddress((void**)&ench,   g_ench);
    cudaGetSymbolAddress((void**)&encl,   g_encl);
    cudaGetSymbolAddress((void**)&encvh,  g_encvh);
    cudaGetSymbolAddress((void**)&encvl,  g_encvl);
    cudaGetSymbolAddress((void**)&dech,   g_dech);
    cudaGetSymbolAddress((void**)&decl,   g_decl);

    cudaFuncSetAttribute(scores_hmma, cudaFuncAttributeMaxDynamicSharedMemorySize, HSMEM);
    cudaFuncSetAttribute(hmma_gemm<HM_NONE, 0>,  cudaFuncAttributeMaxDynamicSharedMemorySize, HSMEM);
    cudaFuncSetAttribute(hmma_gemm<HM_NONE, 1>,  cudaFuncAttributeMaxDynamicSharedMemorySize, HSMEM);
    cudaFuncSetAttribute(hmma_gemm<HM_ROPE, 0>,  cudaFuncAttributeMaxDynamicSharedMemorySize, HSMEM);
    cudaFuncSetAttribute(hmma_gemm<HM_MULXY, 0>, cudaFuncAttributeMaxDynamicSharedMemorySize, HSMEM);

    const long WN = (long)NHH * DD * NN;
    cvt_split<<<(int)(WN / 4 / 256), 256>>>(encoder,   ench,  encl,  WN);
    cvt_split<<<(int)(WN / 4 / 256), 256>>>(encoder_v, encvh, encvl, WN);
    cvt_split<<<(int)(WN / 4 / 256), 256>>>(decoder,   dech,  decl,  WN);

    embed_ln_kernel<<<TT, 256>>>(idx, embed);

    for (int l = 0; l < 2; l++) {
        // x_sparse = relu(x @ encoder) fp32 -> g_xs; QR hi/lo -> g_qrh/l
        hmma_gemm<HM_ROPE, 0><<<dim3(NN / 128, TT / 128, NHH), 256, HSMEM>>>(
            xh, xl, ench, encl, xs, DD, DD, NN, NN,
            0L, (long)DD * NN, (long)TT * NN);

        // scores = mask .* (QR @ QR^T) -> bf16 hi/lo
        scores_hmma<<<dim3(TT / 128, TT / 128, NHH), 256, HSMEM>>>(qrh, qrl, sch, scl);

        // yKV = scores @ x — causal-bounded HMMA
        hmma_gemm<HM_NONE, 1><<<dim3(DD / 128, TT / 128, NHH), 256, HSMEM>>>(
            sch, scl, xh, xl, ykv, TT, TT, DD, DD,
            (long)TT * TT, 0L, (long)TT * DD);

        ln_rows_kernel<<<NHH * TT, 256>>>(ykv);

        // xy = relu(yKV @ encoder_v) * x_sparse -> bf16 hi/lo
        hmma_gemm<HM_MULXY, 0><<<dim3(NN / 128, TT / 128, NHH), 256, HSMEM>>>(
            ykvh, ykvl, encvh, encvl, xs, DD, DD, NN, 0,
            (long)TT * DD, (long)DD * NN, 0L);

        // yMLP partials = xy @ decoder (split-K 16)
        hmma_gemm<HM_NONE, 0><<<dim3(DD / 128, TT / 128, SPLITK), 256, HSMEM>>>(
            xyh, xyl, dech, decl, part, KSPL, NHH * NN, DD, DD,
            (long)KSPL, (long)KSPL * DD, (long)TT * DD);

        mlp_finish_kernel<<<TT, 256>>>();
    }

    sgemm_kernel<EM_NONE><<<dim3(VOC / 128, TT / 128, 1), 256>>>(
        x, lm_head, out, DD, DD, VOC, VOC, 0L, 0L, 0L);
}

// round 9
// speedup vs baseline: 2.8874x; 1.2247x over previous
#include <cuda_runtime.h>
#include <math.h>
#include <stdint.h>

// ---------------- problem constants ----------------
#define NHH   4
#define DD    256
#define NN    8192
#define TT    2048
#define VOC   256
#define SPLITK 16
#define KSPL  2048              // NHH*NN/SPLITK
#define LNEPS 1e-5f
#define TWO_PI_F 6.28318530717958647692f

// ---------------- scratch (static device globals) ----
__device__ float g_x[TT * DD];
__device__ unsigned short g_xh[TT * DD];
__device__ unsigned short g_xl[TT * DD];
__device__ float g_xs[(size_t)NHH * TT * NN];
__device__ unsigned short g_sch[(size_t)NHH * TT * TT];   // scores hi (bf16)
__device__ unsigned short g_scl[(size_t)NHH * TT * TT];   // scores lo (bf16)
__device__ float g_ykv[(size_t)NHH * TT * DD];
__device__ unsigned short g_ykvh[(size_t)NHH * TT * DD];
__device__ unsigned short g_ykvl[(size_t)NHH * TT * DD];
__device__ float g_part[(size_t)SPLITK * TT * DD];
__device__ unsigned short g_qrh[(size_t)NHH * TT * NN];
__device__ unsigned short g_qrl[(size_t)NHH * TT * NN];
__device__ unsigned short g_xyh[(size_t)NHH * TT * NN];
__device__ unsigned short g_xyl[(size_t)NHH * TT * NN];
__device__ unsigned short g_ench[(size_t)NHH * DD * NN];
__device__ unsigned short g_encl[(size_t)NHH * DD * NN];
__device__ unsigned short g_encvh[(size_t)NHH * DD * NN];
__device__ unsigned short g_encvl[(size_t)NHH * DD * NN];
__device__ unsigned short g_dech[(size_t)NHH * NN * DD];
__device__ unsigned short g_decl[(size_t)NHH * NN * DD];

enum { EM_NONE = 0 };
enum { HM_NONE = 0, HM_ROPE = 1, HM_MULXY = 2 };

typedef unsigned long long u64;

// ---------------- packed f32x2 helpers ----------------
__device__ __forceinline__ void ffma2(u64& d, u64 a, u64 b) {
    asm("fma.rn.f32x2 %0, %1, %2, %0;" : "+l"(d) : "l"(a), "l"(b));
}
__device__ __forceinline__ u64 dup2(float x) {
    u64 r;
    asm("mov.b64 %0, {%1, %1};" : "=l"(r) : "r"(__float_as_uint(x)));
    return r;
}
__device__ __forceinline__ void unpack2(u64 v, float& lo, float& hi) {
    unsigned a, b;
    asm("mov.b64 {%0, %1}, %2;" : "=r"(a), "=r"(b) : "l"(v));
    lo = __uint_as_float(a); hi = __uint_as_float(b);
}

// ---------------- bf16 bit helpers ----------------
__device__ __forceinline__ unsigned short f2bf(float x) {
    unsigned u = __float_as_uint(x);
    unsigned r = (u + 0x7FFFu + ((u >> 16) & 1u)) >> 16;
    return (unsigned short)r;
}
__device__ __forceinline__ float bf2f(unsigned short b) {
    return __uint_as_float((unsigned)b << 16);
}
__device__ __forceinline__ unsigned pack_hl(float a, float b,
                                            unsigned short& la, unsigned short& lb) {
    unsigned short ha = f2bf(a), hb = f2bf(b);
    la = f2bf(a - bf2f(ha));
    lb = f2bf(b - bf2f(hb));
    return (unsigned)ha | ((unsigned)hb << 16);
}

// ---------------- warp-MMA helpers ----------------
__device__ __forceinline__ uint32_t smem_to_u32(const void* smem_ptr) {
    uint32_t addr;
    asm("{ .reg .u64 tmp; cvta.to.shared.u64 tmp, %1; cvt.u32.u64 %0, tmp; }"
        : "=r"(addr) : "l"(smem_ptr));
    return addr;
}
__device__ __forceinline__ void ldsm4(uint32_t* r, uint32_t addr) {
    asm volatile("ldmatrix.sync.aligned.m8n8.x4.shared.b16 {%0,%1,%2,%3}, [%4];"
        : "=r"(r[0]), "=r"(r[1]), "=r"(r[2]), "=r"(r[3]) : "r"(addr));
}
__device__ __forceinline__ void ldsm4t(uint32_t* r, uint32_t addr) {
    asm volatile("ldmatrix.sync.aligned.m8n8.x4.trans.shared.b16 {%0,%1,%2,%3}, [%4];"
        : "=r"(r[0]), "=r"(r[1]), "=r"(r[2]), "=r"(r[3]) : "r"(addr));
}
__device__ __forceinline__ void mma16816(float* c, const uint32_t* a, const uint32_t* b) {
    asm volatile(
        "mma.sync.aligned.m16n8k16.row.col.f32.bf16.bf16.f32 "
        "{%0,%1,%2,%3}, {%4,%5,%6,%7}, {%8,%9}, {%0,%1,%2,%3};"
        : "+f"(c[0]), "+f"(c[1]), "+f"(c[2]), "+f"(c[3])
        : "r"(a[0]), "r"(a[1]), "r"(a[2]), "r"(a[3]), "r"(b[0]), "r"(b[1]));
}
#define CP_ASYNC16(dst, src) \
    asm volatile("cp.async.cg.shared.global [%0], [%1], 16;" :: "r"(dst), "l"(src))
#define CP_COMMIT() asm volatile("cp.async.commit_group;" ::: "memory")
#define CP_WAIT(n)  asm volatile("cp.async.wait_group %0;" :: "n"(n) : "memory")

__device__ __forceinline__ uint32_t sw64(uint32_t b)  { return b ^ ((b >> 3) & 0x30); }
__device__ __forceinline__ uint32_t sw128(uint32_t b) { return b ^ ((b >> 3) & 0x70); }
__device__ __forceinline__ uint32_t sw256(uint32_t b) { return b ^ ((b >> 4) & 0x70); }

#define HTILE 16384
#define HSTG  (4 * HTILE)
#define NSTG  3
#define HSMEM (NSTG * HSTG + 1024)

// small-K config: K-chunk 32, 3 stages of 32KB, 2 CTAs/SM
#define H32_A    8192            // 128 rows x 64B (hi or lo)
#define H32_B    8192            // 32 rows x 256B (hi or lo)
#define H32_STG  32768
#define H32_SMEM (3 * H32_STG + 1024)

// ================= HMMA scores kernel (3-stage, single-sync, bf16 hi/lo out) ====
__global__ void __launch_bounds__(256)
scores_hmma(const unsigned short* __restrict__ qh,
            const unsigned short* __restrict__ ql,
            unsigned short* __restrict__ sch,
            unsigned short* __restrict__ scl)
{
    const int br = blockIdx.y;
    const int bc = blockIdx.x;
    const int h  = blockIdx.z;
    if (bc > br) return;

    extern __shared__ char dsm[];
    const int tid  = threadIdx.x;
    const int wid  = tid >> 5;
    const int lane = tid & 31;
    const int wr   = wid & 3;
    const int wc   = wid >> 2;
    const int row0 = br * 128;
    const int col0 = bc * 128;

    const uint32_t raw = smem_to_u32(dsm);
    const uint32_t sb  = (raw + 1023u) & ~1023u;

    const size_t hb = (size_t)h * TT * NN;
    const unsigned short* srcs[4];
    srcs[0] = qh + hb + (size_t)row0 * NN;
    srcs[1] = ql + hb + (size_t)row0 * NN;
    srcs[2] = qh + hb + (size_t)col0 * NN;
    srcs[3] = ql + hb + (size_t)col0 * NN;

    float acc[2][8][4];
#pragma unroll
    for (int mi = 0; mi < 2; mi++)
#pragma unroll
        for (int ni = 0; ni < 8; ni++)
#pragma unroll
            for (int q = 0; q < 4; q++) acc[mi][ni][q] = 0.f;

    const int NITER = NN / 64;

    auto load_stage = [&](int st, int kc0) {
        const uint32_t stg = sb + st * HSTG;
#pragma unroll
        for (int t4 = 0; t4 < 4; t4++) {
            const unsigned short* src = srcs[t4] + kc0;
            const uint32_t tb = stg + t4 * HTILE;
#pragma unroll
            for (int i = 0; i < 4; i++) {
                int idx = i * 256 + tid;
                int r = idx >> 3;
                int c = idx & 7;
                uint32_t dst = tb + sw128(r * 128 + c * 16);
                CP_ASYNC16(dst, src + (size_t)r * NN + c * 8);
            }
        }
    };

    load_stage(0, 0);
    CP_COMMIT();
    load_stage(1, 64);
    CP_COMMIT();

    for (int it = 0; it < NITER; it++) {
        if (it + 1 < NITER) { CP_WAIT(1); }
        else                { CP_WAIT(0); }
        __syncthreads();
        if (it + 2 < NITER) {
            load_stage((it + 2) % NSTG, (it + 2) * 64);
            CP_COMMIT();
        }

        const uint32_t stg = sb + (it % NSTG) * HSTG;
#pragma unroll
        for (int ks = 0; ks < 4; ks++) {
            const int lrow  = lane & 15;
            const int chunk = ks * 2 + (lane >> 4);

            uint32_t ah[2][4], al[2][4];
#pragma unroll
            for (int mi = 0; mi < 2; mi++) {
                int row = wr * 32 + mi * 16 + lrow;
                uint32_t off = sw128(row * 128 + chunk * 16);
                ldsm4(ah[mi], stg + 0 * HTILE + off);
                ldsm4(al[mi], stg + 1 * HTILE + off);
            }

#pragma unroll
            for (int ng = 0; ng < 4; ng++) {
                int row = wc * 64 + ng * 16 + lrow;
                uint32_t off = sw128(row * 128 + chunk * 16);
                uint32_t t0[4], t1[4];
                ldsm4(t0, stg + 2 * HTILE + off);
                ldsm4(t1, stg + 3 * HTILE + off);
                uint32_t bh0[2], bh1[2], bl0[2], bl1[2];
                bh0[0] = t0[0]; bh0[1] = t0[2];
                bh1[0] = t0[1]; bh1[1] = t0[3];
                bl0[0] = t1[0]; bl0[1] = t1[2];
                bl1[0] = t1[1]; bl1[1] = t1[3];
#pragma unroll
                for (int mi = 0; mi < 2; mi++) {
                    mma16816(acc[mi][2 * ng],     ah[mi], bh0);
                    mma16816(acc[mi][2 * ng],     ah[mi], bl0);
                    mma16816(acc[mi][2 * ng],     al[mi], bh0);
                    mma16816(acc[mi][2 * ng + 1], ah[mi], bh1);
                    mma16816(acc[mi][2 * ng + 1], ah[mi], bl1);
                    mma16816(acc[mi][2 * ng + 1], al[mi], bh1);
                }
            }
        }
    }

    // epilogue: strictly-lower mask, write bf16 hi/lo split
    unsigned short* dh = sch + (size_t)h * TT * TT;
    unsigned short* dl = scl + (size_t)h * TT * TT;
    const int rb = row0 + wr * 32;
    const int cb = col0 + wc * 64;
#pragma unroll
    for (int mi = 0; mi < 2; mi++) {
#pragma unroll
        for (int ni = 0; ni < 8; ni++) {
            int r = rb + mi * 16 + (lane >> 2);
            int s = cb + ni * 8 + (lane & 3) * 2;
#pragma unroll
            for (int half = 0; half < 2; half++) {
                int rr = r + half * 8;
                float v0 = (rr > s)     ? acc[mi][ni][half * 2 + 0] : 0.f;
                float v1 = (rr > s + 1) ? acc[mi][ni][half * 2 + 1] : 0.f;
                unsigned short l0, l1;
                unsigned hv = pack_hl(v0, v1, l0, l1);
                size_t base = (size_t)rr * TT + s;
                *(unsigned*)(dh + base) = hv;
                *(unsigned*)(dl + base) = (unsigned)l0 | ((unsigned)l1 << 16);
            }
        }
    }
}

// ================= generic HMMA GEMM (K-chunk 32, 3-stage, 2 CTAs/SM) ==========
// A [M,K] k-contig (64B rows, SW64), B [K,N] n-contig (256B rows, SW256).
// acc = Ah*Bh + Ah*Bl + Al*Bh (fp32).
template <int HM, int CAUSAL>
__global__ void __launch_bounds__(256, 2)
hmma_gemm(const unsigned short* __restrict__ Ah, const unsigned short* __restrict__ Al,
          const unsigned short* __restrict__ Bh, const unsigned short* __restrict__ Bl,
          float* __restrict__ C, int K, int lda, int ldb, int ldc,
          long offAz, long offBz, long offCz)
{
    const int z = blockIdx.z;
    Ah += (long)z * offAz;
    Al += (long)z * offAz;
    Bh += (long)z * offBz;
    Bl += (long)z * offBz;
    if (HM != HM_MULXY) C += (long)z * offCz;

    extern __shared__ char dsm[];
    const int tid  = threadIdx.x;
    const int wid  = tid >> 5;
    const int lane = tid & 31;
    const int wr   = wid & 3;
    const int wc   = wid >> 2;
    const int row0 = blockIdx.y * 128;
    const int col0 = blockIdx.x * 128;

    const uint32_t raw = smem_to_u32(dsm);
    const uint32_t sb  = (raw + 1023u) & ~1023u;

    const unsigned short* A0 = Ah + (size_t)row0 * lda;
    const unsigned short* A1 = Al + (size_t)row0 * lda;

    float acc[2][8][4];
#pragma unroll
    for (int mi = 0; mi < 2; mi++)
#pragma unroll
        for (int ni = 0; ni < 8; ni++)
#pragma unroll
            for (int q = 0; q < 4; q++) acc[mi][ni][q] = 0.f;

    const int NITER = (CAUSAL ? (row0 + 128) : K) / 32;

    auto load_stage = [&](int st, int k0) {
        const uint32_t stg = sb + st * H32_STG;
#pragma unroll
        for (int i = 0; i < 2; i++) {
            int idx = i * 256 + tid;
            int r = idx >> 2;
            int c = idx & 3;
            uint32_t off = sw64(r * 64 + c * 16);
            CP_ASYNC16(stg + off,          A0 + (size_t)r * lda + k0 + c * 8);
            CP_ASYNC16(stg + H32_A + off,  A1 + (size_t)r * lda + k0 + c * 8);
        }
#pragma unroll
        for (int i = 0; i < 2; i++) {
            int idx = i * 256 + tid;
            int r = idx >> 4;
            int c = idx & 15;
            uint32_t off = sw256(r * 256 + c * 16);
            CP_ASYNC16(stg + 2 * H32_A + off,         Bh + (size_t)(k0 + r) * ldb + col0 + c * 8);
            CP_ASYNC16(stg + 2 * H32_A + H32_B + off, Bl + (size_t)(k0 + r) * ldb + col0 + c * 8);
        }
    };

    load_stage(0, 0);
    CP_COMMIT();
    if (NITER > 1) { load_stage(1, 32); CP_COMMIT(); }

    for (int it = 0; it < NITER; it++) {
        if (it + 1 < NITER) { CP_WAIT(1); }
        else                { CP_WAIT(0); }
        __syncthreads();
        if (it + 2 < NITER) {
            load_stage((it + 2) % 3, (it + 2) * 32);
            CP_COMMIT();
        }

        const uint32_t stg = sb + (it % 3) * H32_STG;
#pragma unroll
        for (int ks = 0; ks < 2; ks++) {
            const int lrow = lane & 15;

            uint32_t ah[2][4], al[2][4];
#pragma unroll
            for (int mi = 0; mi < 2; mi++) {
                int row = wr * 32 + mi * 16 + lrow;
                uint32_t off = sw64(row * 64 + (ks * 2 + (lane >> 4)) * 16);
                ldsm4(ah[mi], stg + off);
                ldsm4(al[mi], stg + H32_A + off);
            }

#pragma unroll
            for (int ng = 0; ng < 4; ng++) {
                int kk = ks * 16 + lrow;
                int nc = wc * 64 + ng * 16 + (lane >> 4) * 8;
                uint32_t off = sw256(kk * 256 + nc * 2);
                uint32_t t0[4], t1[4];
                ldsm4t(t0, stg + 2 * H32_A + off);
                ldsm4t(t1, stg + 2 * H32_A + H32_B + off);
                uint32_t bh0[2], bh1[2], bl0[2], bl1[2];
                bh0[0] = t0[0]; bh0[1] = t0[1];
                bh1[0] = t0[2]; bh1[1] = t0[3];
                bl0[0] = t1[0]; bl0[1] = t1[1];
                bl1[0] = t1[2]; bl1[1] = t1[3];
#pragma unroll
                for (int mi = 0; mi < 2; mi++) {
                    mma16816(acc[mi][2 * ng],     ah[mi], bh0);
                    mma16816(acc[mi][2 * ng],     ah[mi], bl0);
                    mma16816(acc[mi][2 * ng],     al[mi], bh0);
                    mma16816(acc[mi][2 * ng + 1], ah[mi], bh1);
                    mma16816(acc[mi][2 * ng + 1], ah[mi], bl1);
                    mma16816(acc[mi][2 * ng + 1], al[mi], bh1);
                }
            }
        }
    }

    // ---------------- epilogues ----------------
    const int rb = row0 + wr * 32;
    const int cb = col0 + wc * 64;

    if (HM == HM_NONE) {
#pragma unroll
        for (int mi = 0; mi < 2; mi++) {
#pragma unroll
            for (int ni = 0; ni < 8; ni++) {
                int r = rb + mi * 16 + (lane >> 2);
                int s = cb + ni * 8 + (lane & 3) * 2;
                *(float2*)(C + (size_t)r * ldc + s) =
                    make_float2(acc[mi][ni][0], acc[mi][ni][1]);
                *(float2*)(C + (size_t)(r + 8) * ldc + s) =
                    make_float2(acc[mi][ni][2], acc[mi][ni][3]);
            }
        }
    } else if (HM == HM_ROPE) {
        unsigned short* Qh = g_qrh + (size_t)z * TT * NN;
        unsigned short* Ql = g_qrl + (size_t)z * TT * NN;
#pragma unroll
        for (int ni = 0; ni < 8; ni++) {
            int n0 = cb + ni * 8 + (lane & 3) * 2;
            float fr = (float)exp2(-(double)n0 / 512.0) / TWO_PI_F;
#pragma unroll
            for (int mi = 0; mi < 2; mi++) {
                int rbase = rb + mi * 16 + (lane >> 2);
#pragma unroll
                for (int half = 0; half < 2; half++) {
                    int r = rbase + half * 8;
                    float v0 = fmaxf(acc[mi][ni][half * 2 + 0], 0.f);
                    float v1 = fmaxf(acc[mi][ni][half * 2 + 1], 0.f);
                    *(float2*)(C + (size_t)r * ldc + n0) = make_float2(v0, v1);
                    float ph   = (float)r * fr;
                    float frac = ph - floorf(ph);
                    float ang  = frac * TWO_PI_F;
                    float si, co;
                    sincosf(ang, &si, &co);
                    float q0 = v0 * co - v1 * si;
                    float q1 = v1 * co + v0 * si;
                    unsigned short l0, l1;
                    unsigned hv = pack_hl(q0, q1, l0, l1);
                    *(unsigned*)(Qh + (size_t)r * NN + n0) = hv;
                    *(unsigned*)(Ql + (size_t)r * NN + n0) = (unsigned)l0 | ((unsigned)l1 << 16);
                }
            }
        }
    } else if (HM == HM_MULXY) {
        const float* xsrc = g_xs + (size_t)z * TT * NN;
        unsigned short* Xh = g_xyh;
        unsigned short* Xl = g_xyl;
        const int colz = z * NN;
#pragma unroll
        for (int mi = 0; mi < 2; mi++) {
#pragma unroll
            for (int ni = 0; ni < 8; ni++) {
                int n0 = cb + ni * 8 + (lane & 3) * 2;
                int rbase = rb + mi * 16 + (lane >> 2);
#pragma unroll
                for (int half = 0; half < 2; half++) {
                    int r = rbase + half * 8;
                    float2 xv = *(const float2*)(xsrc + (size_t)r * NN + n0);
                    float v0 = fmaxf(acc[mi][ni][half * 2 + 0], 0.f) * xv.x;
                    float v1 = fmaxf(acc[mi][ni][half * 2 + 1], 0.f) * xv.y;
                    unsigned short l0, l1;
                    unsigned hv = pack_hl(v0, v1, l0, l1);
                    size_t base = (size_t)r * (NHH * NN) + colz + n0;
                    *(unsigned*)(Xh + base) = hv;
                    *(unsigned*)(Xl + base) = (unsigned)l0 | ((unsigned)l1 << 16);
                }
            }
        }
    }
}

// ---------------- weight split conversion ----------------
__global__ void cvt_split(const float* __restrict__ src,
                          unsigned short* __restrict__ h,
                          unsigned short* __restrict__ l, long n)
{
    long i = ((long)blockIdx.x * blockDim.x + threadIdx.x) * 4;
    if (i >= n) return;
    float4 v = *(const float4*)(src + i);
    unsigned short l0, l1, l2, l3;
    uint2 hv, lv;
    hv.x = pack_hl(v.x, v.y, l0, l1);
    hv.y = pack_hl(v.z, v.w, l2, l3);
    lv.x = (unsigned)l0 | ((unsigned)l1 << 16);
    lv.y = (unsigned)l2 | ((unsigned)l3 << 16);
    *(uint2*)(h + i) = hv;
    *(uint2*)(l + i) = lv;
}

// ---------------- block reduction over 256 threads ----------------
__device__ __forceinline__ float blk_sum(float v, float* sb) {
    int tid = threadIdx.x;
#pragma unroll
    for (int o = 16; o > 0; o >>= 1) v += __shfl_down_sync(0xffffffffu, v, o);
    if ((tid & 31) == 0) sb[tid >> 5] = v;
    __syncthreads();
    if (tid < 32) {
        float w = (tid < 8) ? sb[tid] : 0.f;
#pragma unroll
        for (int o = 4; o > 0; o >>= 1) w += __shfl_down_sync(0xffffffffu, w, o);
        if (tid == 0) sb[0] = w;
    }
    __syncthreads();
    float r = sb[0];
    __syncthreads();
    return r;
}

// ---------------- fp32 SGEMM (kept for lm_head) ----------------
template <int MODE>
__global__ void __launch_bounds__(256)
sgemm_kernel(const float* __restrict__ A, const float* __restrict__ B,
             float* __restrict__ C, int K,
             int lda, int ldb, int ldc,
             long offAz, long offBz, long offCz)
{
    const int z = blockIdx.z;
    A += (long)z * offAz;
    B += (long)z * offBz;
    C += (long)z * offCz;

    const int br = blockIdx.y, bc = blockIdx.x;
    const int row0 = br * 128, col0 = bc * 128;
    const int tid = threadIdx.x;
    const int tx = tid & 15, ty = tid >> 4;

    __shared__ __align__(16) float As[8][132];
    __shared__ __align__(16) float Bs[8][132];

    u64 acc2[8][4];
#pragma unroll
    for (int i = 0; i < 8; i++) {
#pragma unroll
        for (int j = 0; j < 4; j++) acc2[i][j] = 0ull;
    }

    const int ar = tid >> 1;
    const int ak = (tid & 1) * 4;
    const int bkr = tid >> 5;
    const int bcc = (tid & 31) * 4;

    const float* Ap = A + (long)(row0 + ar) * lda + ak;
    const float* Bp = B + (long)bkr * ldb + col0 + bcc;

    float4 a4 = *(const float4*)Ap;  Ap += 8;
    float4 b4 = *(const float4*)Bp;  Bp += (long)8 * ldb;

    for (int k0 = 0; k0 < K; k0 += 8) {
        As[ak + 0][ar] = a4.x; As[ak + 1][ar] = a4.y;
        As[ak + 2][ar] = a4.z; As[ak + 3][ar] = a4.w;
        Bs[bkr][bcc + 0] = b4.x; Bs[bkr][bcc + 1] = b4.y;
        Bs[bkr][bcc + 2] = b4.z; Bs[bkr][bcc + 3] = b4.w;
        __syncthreads();

        if (k0 + 8 < K) {
            a4 = *(const float4*)Ap;  Ap += 8;
            b4 = *(const float4*)Bp;  Bp += (long)8 * ldb;
        }

#pragma unroll
        for (int k = 0; k < 8; k++) {
            float a[8];
            *(float4*)&a[0] = *(const float4*)&As[k][ty * 8];
            *(float4*)&a[4] = *(const float4*)&As[k][ty * 8 + 4];
            ulonglong2 bu0 = *(const ulonglong2*)&Bs[k][tx * 8];
            ulonglong2 bu1 = *(const ulonglong2*)&Bs[k][tx * 8 + 4];
            u64 b2[4];
            b2[0] = bu0.x; b2[1] = bu0.y; b2[2] = bu1.x; b2[3] = bu1.y;
            u64 a2[8];
#pragma unroll
            for (int i = 0; i < 8; i++) a2[i] = dup2(a[i]);
#pragma unroll
            for (int i = 0; i < 8; i++) {
#pragma unroll
                for (int j = 0; j < 4; j++) ffma2(acc2[i][j], a2[i], b2[j]);
            }
        }
        __syncthreads();
    }

    float acc[8][8];
#pragma unroll
    for (int i = 0; i < 8; i++) {
#pragma unroll
        for (int j = 0; j < 4; j++) unpack2(acc2[i][j], acc[i][2 * j], acc[i][2 * j + 1]);
    }

#pragma unroll
    for (int i = 0; i < 8; i++) {
        long base = (long)(row0 + ty * 8 + i) * ldc + col0 + tx * 8;
        *(float4*)(C + base)     = make_float4(acc[i][0], acc[i][1], acc[i][2], acc[i][3]);
        *(float4*)(C + base + 4) = make_float4(acc[i][4], acc[i][5], acc[i][6], acc[i][7]);
    }
}

// ---------------- small elementwise kernels ----------------
__global__ void embed_ln_kernel(const int* __restrict__ idx,
                                const float* __restrict__ embed)
{
    __shared__ float sb[8];
    int t = blockIdx.x, d = threadIdx.x;
    float v   = embed[idx[t] * DD + d];
    float mu  = blk_sum(v, sb) * (1.f / DD);
    float dv  = v - mu;
    float var = blk_sum(dv * dv, sb) * (1.f / DD);
    float o = dv / sqrtf(var + LNEPS);
    g_x[t * DD + d] = o;
    unsigned short hh = f2bf(o);
    g_xh[t * DD + d] = hh;
    g_xl[t * DD + d] = f2bf(o - bf2f(hh));
}

__global__ void ln_rows_kernel(float* __restrict__ buf)
{
    __shared__ float sb[8];
    long r = blockIdx.x;
    int  d = threadIdx.x;
    float v   = buf[r * DD + d];
    float mu  = blk_sum(v, sb) * (1.f / DD);
    float dv  = v - mu;
    float var = blk_sum(dv * dv, sb) * (1.f / DD);
    float o = dv / sqrtf(var + LNEPS);
    buf[r * DD + d] = o;
    unsigned short hh = f2bf(o);
    g_ykvh[r * DD + d] = hh;
    g_ykvl[r * DD + d] = f2bf(o - bf2f(hh));
}

__global__ void mlp_finish_kernel()
{
    __shared__ float sb[8];
    int t = blockIdx.x, d = threadIdx.x;
    float s = 0.f;
#pragma unroll
    for (int kz = 0; kz < SPLITK; kz++)
        s += g_part[(size_t)kz * TT * DD + t * DD + d];

    float mu  = blk_sum(s, sb) * (1.f / DD);
    float dv  = s - mu;
    float var = blk_sum(dv * dv, sb) * (1.f / DD);
    float a   = dv / sqrtf(var + LNEPS);

    float b = g_x[t * DD + d] + a;
    mu  = blk_sum(b, sb) * (1.f / DD);
    dv  = b - mu;
    var = blk_sum(dv * dv, sb) * (1.f / DD);
    float o = dv / sqrtf(var + LNEPS);
    g_x[t * DD + d] = o;
    unsigned short hh = f2bf(o);
    g_xh[t * DD + d] = hh;
    g_xl[t * DD + d] = f2bf(o - bf2f(hh));
}

// ---------------- launch ----------------
extern "C" void kernel_launch(void* const* d_in, const int* in_sizes, int n_in,
                              void* d_out, int out_size)
{
    (void)in_sizes; (void)n_in; (void)out_size;
    const int*   idx       = (const int*)d_in[0];
    const float* embed     = (const float*)d_in[1];
    const float* encoder   = (const float*)d_in[2];
    const float* encoder_v = (const float*)d_in[3];
    const float* decoder   = (const float*)d_in[4];
    const float* lm_head   = (const float*)d_in[5];
    float*       out       = (float*)d_out;

    float* x = 0; float* xs = 0; float* ykv = 0; float* part = 0;
    unsigned short *sch = 0, *scl = 0;
    unsigned short *qrh = 0, *qrl = 0, *xyh = 0, *xyl = 0;
    unsigned short *xh = 0, *xl = 0, *ykvh = 0, *ykvl = 0;
    unsigned short *ench = 0, *encl = 0, *encvh = 0, *encvl = 0, *dech = 0, *decl = 0;
    cudaGetSymbolAddress((void**)&x,      g_x);
    cudaGetSymbolAddress((void**)&xs,     g_xs);
    cudaGetSymbolAddress((void**)&sch,    g_sch);
    cudaGetSymbolAddress((void**)&scl,    g_scl);
    cudaGetSymbolAddress((void**)&ykv,    g_ykv);
    cudaGetSymbolAddress((void**)&part,   g_part);
    cudaGetSymbolAddress((void**)&qrh,    g_qrh);
    cudaGetSymbolAddress((void**)&qrl,    g_qrl);
    cudaGetSymbolAddress((void**)&xyh,    g_xyh);
    cudaGetSymbolAddress((void**)&xyl,    g_xyl);
    cudaGetSymbolAddress((void**)&xh,     g_xh);
    cudaGetSymbolAddress((void**)&xl,     g_xl);
    cudaGetSymbolAddress((void**)&ykvh,   g_ykvh);
    cudaGetSymbolAddress((void**)&ykvl,   g_ykvl);
    cudaGetSymbolAddress((void**)&ench,   g_ench);
    cudaGetSymbolAddress((void**)&encl,   g_encl);
    cudaGetSymbolAddress((void**)&encvh,  g_encvh);
    cudaGetSymbolAddress((void**)&encvl,  g_encvl);
    cudaGetSymbolAddress((void**)&dech,   g_dech);
    cudaGetSymbolAddress((void**)&decl,   g_decl);

    cudaFuncSetAttribute(scores_hmma, cudaFuncAttributeMaxDynamicSharedMemorySize, HSMEM);
    cudaFuncSetAttribute(hmma_gemm<HM_NONE, 0>,  cudaFuncAttributeMaxDynamicSharedMemorySize, H32_SMEM);
    cudaFuncSetAttribute(hmma_gemm<HM_NONE, 1>,  cudaFuncAttributeMaxDynamicSharedMemorySize, H32_SMEM);
    cudaFuncSetAttribute(hmma_gemm<HM_ROPE, 0>,  cudaFuncAttributeMaxDynamicSharedMemorySize, H32_SMEM);
    cudaFuncSetAttribute(hmma_gemm<HM_MULXY, 0>, cudaFuncAttributeMaxDynamicSharedMemorySize, H32_SMEM);

    const long WN = (long)NHH * DD * NN;
    cvt_split<<<(int)(WN / 4 / 256), 256>>>(encoder,   ench,  encl,  WN);
    cvt_split<<<(int)(WN / 4 / 256), 256>>>(encoder_v, encvh, encvl, WN);
    cvt_split<<<(int)(WN / 4 / 256), 256>>>(decoder,   dech,  decl,  WN);

    embed_ln_kernel<<<TT, 256>>>(idx, embed);

    for (int l = 0; l < 2; l++) {
        // x_sparse = relu(x @ encoder) fp32 -> g_xs; QR hi/lo -> g_qrh/l
        hmma_gemm<HM_ROPE, 0><<<dim3(NN / 128, TT / 128, NHH), 256, H32_SMEM>>>(
            xh, xl, ench, encl, xs, DD, DD, NN, NN,
            0L, (long)DD * NN, (long)TT * NN);

        // scores = mask .* (QR @ QR^T) -> bf16 hi/lo
        scores_hmma<<<dim3(TT / 128, TT / 128, NHH), 256, HSMEM>>>(qrh, qrl, sch, scl);

        // yKV = scores @ x — causal-bounded HMMA
        hmma_gemm<HM_NONE, 1><<<dim3(DD / 128, TT / 128, NHH), 256, H32_SMEM>>>(
            sch, scl, xh, xl, ykv, TT, TT, DD, DD,
            (long)TT * TT, 0L, (long)TT * DD);

        ln_rows_kernel<<<NHH * TT, 256>>>(ykv);

        // xy = relu(yKV @ encoder_v) * x_sparse -> bf16 hi/lo
        hmma_gemm<HM_MULXY, 0><<<dim3(NN / 128, TT / 128, NHH), 256, H32_SMEM>>>(
            ykvh, ykvl, encvh, encvl, xs, DD, DD, NN, 0,
            (long)TT * DD, (long)DD * NN, 0L);

        // yMLP partials = xy @ decoder (split-K 16)
        hmma_gemm<HM_NONE, 0><<<dim3(DD / 128, TT / 128, SPLITK), 256, H32_SMEM>>>(
            xyh, xyl, dech, decl, part, KSPL, NHH * NN, DD, DD,
            (long)KSPL, (long)KSPL * DD, (long)TT * DD);

        mlp_finish_kernel<<<TT, 256>>>();
    }

    sgemm_kernel<EM_NONE><<<dim3(VOC / 128, TT / 128, 1), 256>>>(
        x, lm_head, out, DD, DD, VOC, VOC, 0L, 0L, 0L);
}